// round 15
// baseline (speedup 1.0000x reference)
#include <cuda_runtime.h>
#include <cuda_fp16.h>
#include <math.h>

#define H_ 16
#define D_ 64
#define R_ 2048
#define S_ 64
#define B_ 2
#define E_ 1024
#define Z_ 64
#define SCALE_ 0.125f
#define MROWS (R_*B_)   /* 4096 */
#define SPLITS 8
#define TOTLEN (S_+R_)  /* 2112 */

// ---------------- scratch (device globals: allocation-free) ----------------
__device__ __half g_xp[MROWS*E_];
__device__ __half g_attnp[MROWS*E_];
__device__ __half g_Wqp[E_*E_];
__device__ __half g_Wkp[E_*E_];
__device__ __half g_Wvp[E_*E_];
__device__ __half g_Wop[E_*E_];
__device__ __half g_qp[B_*H_*R_*D_];
__device__ __half g_kp[B_*H_*R_*D_];
__device__ __half g_vt[B_*H_*D_*R_];
__device__ __half g_r0p[H_*Z_*D_];
__device__ __half g_k2p[B_*H_*S_*D_];
__device__ __half g_v2t[B_*H_*D_*S_];
__device__ unsigned char g_idx8[B_*TOTLEN*R_];
__device__ float g_sumx2[B_*H_*S_*D_];
__device__ float g_pacc[B_*H_*SPLITS*S_*D_];
__device__ float g_pm[B_*H_*SPLITS*S_];
__device__ float g_pl[B_*H_*SPLITS*S_];

// ---------------- helpers ---------------------------------------------------
__device__ __forceinline__ unsigned packh2(float lo, float hi){
    unsigned u;
    asm("{.reg .f16 l,h;\n cvt.rn.f16.f32 l,%1;\n cvt.rn.f16.f32 h,%2;\n mov.b32 %0,{l,h};}\n"
        : "=r"(u) : "f"(lo), "f"(hi));
    return u;
}
__device__ __forceinline__ unsigned sm2u(const void* p){
    return (unsigned)__cvta_generic_to_shared(p);
}
__device__ __forceinline__ void ldsm4(unsigned* r, unsigned addr){
    asm volatile("ldmatrix.sync.aligned.m8n8.x4.shared.b16 {%0,%1,%2,%3},[%4];"
        : "=r"(r[0]), "=r"(r[1]), "=r"(r[2]), "=r"(r[3]) : "r"(addr));
}
__device__ __forceinline__ void mma_f16(float* c, const unsigned* a,
        unsigned b0, unsigned b1){
    asm volatile(
        "mma.sync.aligned.m16n8k16.row.col.f32.f16.f16.f32 "
        "{%0,%1,%2,%3},{%4,%5,%6,%7},{%8,%9},{%0,%1,%2,%3};"
        : "+f"(c[0]), "+f"(c[1]), "+f"(c[2]), "+f"(c[3])
        : "r"(a[0]), "r"(a[1]), "r"(a[2]), "r"(a[3]), "r"(b0), "r"(b1));
}
__device__ __forceinline__ void cp16(void* dst, const void* src){
    unsigned d = (unsigned)__cvta_generic_to_shared(dst);
    asm volatile("cp.async.cg.shared.global [%0],[%1],16;" :: "r"(d), "l"(src));
}
#define CP_COMMIT() asm volatile("cp.async.commit_group;" ::: "memory")
#define CP_WAIT0()  asm volatile("cp.async.wait_group 0;" ::: "memory")
#define CP_WAIT1()  asm volatile("cp.async.wait_group 1;" ::: "memory")

#define LDSM_OFFS()                                                          \
    int arow = (lane&7) + ((lane>>3)&1)*8;                                   \
    int akh  = ((lane>>4)&1)*8;                                              \
    int brow = (lane&7) + ((lane>>4)&1)*8;                                   \
    int bkh  = ((lane>>3)&1)*8;

// -------- pre-conversion kernels -------------------------------------------
__global__ __launch_bounds__(256) void cvtA_kernel(const float* __restrict__ src,
        __half* __restrict__ dst){
    size_t i = (size_t)blockIdx.x*256 + threadIdx.x;
    size_t m = i >> 8; int kq = (int)(i & 255) * 4;
    float4 v = *(const float4*)(src + m*E_ + kq);
    uint2 u; u.x = packh2(v.x, v.y); u.y = packh2(v.z, v.w);
    *(uint2*)&dst[m*E_ + kq] = u;
}
__global__ void cvtW_kernel(const float* __restrict__ W, __half* __restrict__ out){
    __shared__ float tile[32][33];
    int k0 = blockIdx.y*32, n0 = blockIdx.x*32;
    int tx = threadIdx.x, ty = threadIdx.y;  // 32 x 8
    #pragma unroll
    for (int j=0;j<4;j++)
        tile[ty+8*j][tx] = W[(size_t)(k0+ty+8*j)*E_ + n0 + tx];
    __syncthreads();
    #pragma unroll
    for (int j=0;j<4;j++){
        int n = n0 + ty + 8*j;
        out[(size_t)n*E_ + k0 + tx] = __float2half_rn(tile[tx][ty+8*j]);
    }
}

// ---------------- fp16 GEMM + fused epilogue (3-stage pipeline, R11) --------
#define GSTG 10240
#define GEMM_SMEM_BYTES (3*GSTG*2)   /* 61440 */

__device__ __forceinline__ void g_stage_h(__half* smh, int s,
        const __half* Ag, const __half* Wg, int t){
    __half* base = smh + s*GSTG;
    #pragma unroll
    for (int j=0;j<2;j++){
        int c = t + 256*j; int row = c>>2, seg = c&3;   // 128 rows x 4 segs (BK=32)
        cp16(base + row*40 + seg*8, Ag + (size_t)row*E_ + seg*8);
        cp16(base + 5120 + row*40 + seg*8, Wg + (size_t)row*E_ + seg*8);
    }
}

__global__ __launch_bounds__(256) void gemm_fused(const __half* __restrict__ A,
        const __half* __restrict__ W, const float* __restrict__ bias,
        float* __restrict__ outF, int mode,
        const float* __restrict__ gg, const float* __restrict__ bb){
    extern __shared__ __half smh[];
    int t = threadIdx.x, lane = t & 31, w = t >> 5;
    int wm = w >> 1, wn = w & 1;
    int tq = lane >> 2, te = lane & 3;
    LDSM_OFFS();
    int row0 = blockIdx.y * 128, n0 = blockIdx.x * 128;
    const __half* Abase = A + (size_t)row0*E_;
    const __half* Wbase = W + (size_t)n0*E_;

    float acc[2][8][4];
    #pragma unroll
    for (int m=0;m<2;m++)
        #pragma unroll
        for (int n=0;n<8;n++)
            #pragma unroll
            for (int j=0;j<4;j++) acc[m][n][j]=0.f;

    g_stage_h(smh, 0, Abase, Wbase, t); CP_COMMIT();
    g_stage_h(smh, 1, Abase + 32, Wbase + 32, t); CP_COMMIT();

    for (int it=0; it<32; it++){
        if (it < 31){ CP_WAIT1(); } else { CP_WAIT0(); }
        __syncthreads();
        if (it + 2 < 32){
            g_stage_h(smh, (it+2)%3, Abase + (it+2)*32, Wbase + (it+2)*32, t);
            CP_COMMIT();
        }
        __half* As = smh + (it%3)*GSTG;
        __half* Bs = As + 5120;
        #pragma unroll
        for (int ks2=0; ks2<2; ks2++){
            int k0 = ks2*16;
            unsigned a[2][4];
            ldsm4(a[0], sm2u(As + (wm*32 +      arow)*40 + k0 + akh));
            ldsm4(a[1], sm2u(As + (wm*32 + 16 + arow)*40 + k0 + akh));
            #pragma unroll
            for (int p=0; p<4; p++){
                unsigned bbf[4];
                ldsm4(bbf, sm2u(Bs + (wn*64 + p*16 + brow)*40 + k0 + bkh));
                mma_f16(acc[0][2*p],   a[0], bbf[0], bbf[1]);
                mma_f16(acc[0][2*p+1], a[0], bbf[2], bbf[3]);
                mma_f16(acc[1][2*p],   a[1], bbf[0], bbf[1]);
                mma_f16(acc[1][2*p+1], a[1], bbf[2], bbf[3]);
            }
        }
        __syncthreads();
    }

    int h = blockIdx.x*2 + wn;
    #pragma unroll
    for (int mf=0; mf<2; mf++){
        #pragma unroll
        for (int rsel=0; rsel<2; rsel++){
            int m = row0 + wm*32 + mf*16 + tq + rsel*8;
            float v[16];
            #pragma unroll
            for (int nf=0; nf<8; nf++){
                int c = nf*8 + 2*te;
                v[2*nf]   = acc[mf][nf][2*rsel]   + __ldg(&bias[h*64 + c]);
                v[2*nf+1] = acc[mf][nf][2*rsel+1] + __ldg(&bias[h*64 + c + 1]);
            }
            if (mode == 3){
                #pragma unroll
                for (int nf=0; nf<8; nf++)
                    *(float2*)&outF[(size_t)m*E_ + h*64 + nf*8 + 2*te] =
                        make_float2(v[2*nf], v[2*nf+1]);
            } else if (mode == 0){
                int r = m>>1, b = m&1, bh = b*H_ + h;
                __half* dst = g_qp + ((size_t)bh*R_ + r)*64;
                #pragma unroll
                for (int nf=0; nf<8; nf++){
                    int c = nf*8 + 2*te;
                    *(unsigned*)&dst[c] = packh2(v[2*nf]*SCALE_, v[2*nf+1]*SCALE_);
                }
            } else {
                int r = m>>1, b = m&1, bh = b*H_ + h;
                float s = 0.f;
                #pragma unroll
                for (int i=0;i<16;i++) s += v[i];
                s += __shfl_xor_sync(0xffffffffu, s, 1);
                s += __shfl_xor_sync(0xffffffffu, s, 2);
                float mean = s*(1.f/64.f);
                float var = 0.f;
                #pragma unroll
                for (int i=0;i<16;i++){ float d = v[i]-mean; var += d*d; }
                var += __shfl_xor_sync(0xffffffffu, var, 1);
                var += __shfl_xor_sync(0xffffffffu, var, 2);
                float scl = rsqrtf(var*(1.f/64.f) + 1e-5f);
                if (mode == 1){
                    __half* dst = g_kp + ((size_t)bh*R_ + r)*64;
                    #pragma unroll
                    for (int nf=0; nf<8; nf++){
                        int c = nf*8 + 2*te;
                        *(unsigned*)&dst[c] = packh2(
                            (v[2*nf]-mean)*scl*__ldg(&gg[c]) + __ldg(&bb[c]),
                            (v[2*nf+1]-mean)*scl*__ldg(&gg[c+1]) + __ldg(&bb[c+1]));
                    }
                } else {
                    #pragma unroll
                    for (int nf=0; nf<8; nf++){
                        int c = nf*8 + 2*te;
                        g_vt[((size_t)bh*64 + c)*R_ + r] = __float2half_rn(
                            (v[2*nf]-mean)*scl*__ldg(&gg[c]) + __ldg(&bb[c]));
                        g_vt[((size_t)bh*64 + c+1)*R_ + r] = __float2half_rn(
                            (v[2*nf+1]-mean)*scl*__ldg(&gg[c+1]) + __ldg(&bb[c+1]));
                    }
                }
            }
        }
    }
}

// -------- r0p[h][z][d] = fp16( rel_emb0@Wr0 + br0 ) -------------------------
__global__ __launch_bounds__(64) void r0_kernel(const float* __restrict__ rel_emb0,
        const float* __restrict__ Wr0, const float* __restrict__ br0){
    int z = blockIdx.x >> 4, h = blockIdx.x & 15;
    int d = threadIdx.x;
    float a = br0[h*64+d];
    #pragma unroll 8
    for (int c=0;c<64;c++) a += rel_emb0[z*64+c]*Wr0[c*E_ + h*64 + d];
    g_r0p[(h*Z_ + z)*64 + d] = __float2half_rn(a);
}

// -------- compress rel_idx (int32 < 64) to u8 -------------------------------
__global__ __launch_bounds__(256) void idx8_kernel(const int* __restrict__ rel){
    size_t i = (size_t)blockIdx.x*256 + threadIdx.x;
    int4 v = ((const int4*)rel)[i];
    uchar4 u; u.x=(unsigned char)v.x; u.y=(unsigned char)v.y;
    u.z=(unsigned char)v.z; u.w=(unsigned char)v.w;
    ((uchar4*)g_idx8)[i] = u;
}

// ====== fp16 main attention: 128q/CTA, 256 thr, 8 warps (1 mf/warp) =========
// halves: HKB(0)=0, HKB(1)=4608, HVB(0)=9216, HVB(1)=13824 (tiles 64x72)
// floats: MQR at float idx 9216 (128 x 65)
#define HKB(b) ((b)*4608)
#define HVB(b) (9216 + (b)*4608)
#define MQRF   9216
#define MAIN_SMEM_BYTES (36864 + 128*65*4)   /* 70144 */

// 256-thread staging: K/V tiles are 512 chunks each -> j<2
__device__ __forceinline__ void stage_kv_h(__half* smh, int kbo, int vbo,
        const __half* kg, const __half* vg, size_t vstride, int t){
    #pragma unroll
    for (int j=0;j<2;j++){
        int c = t + 256*j; int row = c>>3, seg = c&7;
        cp16(smh + kbo + row*72 + seg*8, kg + (size_t)row*64 + seg*8);
        cp16(smh + vbo + row*72 + seg*8, vg + (size_t)row*vstride + seg*8);
    }
}

__global__ __launch_bounds__(256,2) void attn_main_kernel(){
    extern __shared__ char smraw[];
    __half* smh = (__half*)smraw;
    float* smf = (float*)smraw;
    int t = threadIdx.x, lane = t & 31, w = t >> 5;   // 8 warps
    int tq = lane >> 2, te = lane & 3;
    LDSM_OFFS();
    int b = blockIdx.z, h = blockIdx.y, bh = b*H_ + h;
    int q0 = blockIdx.x * 128;
    int rw = w*16 + tq;          // warp's first q-row (local), rows rw and rw+8

    {   // Q: 128x64 = 1024 chunks (j<4); r0: 64x64 = 512 chunks (j<2)
        const __half* qg = g_qp + ((size_t)bh*R_ + q0)*64;
        const __half* rg = g_r0p + (size_t)h*Z_*64;
        #pragma unroll
        for (int j=0;j<4;j++){
            int c = t + 256*j; int row = c>>3, seg = c&7;
            cp16(smh + row*72 + seg*8, qg + (size_t)row*64 + seg*8);
        }
        #pragma unroll
        for (int j=0;j<2;j++){
            int c = t + 256*j; int row = c>>3, seg = c&7;
            cp16(smh + HVB(0) + row*72 + seg*8, rg + (size_t)row*64 + seg*8);
        }
    }
    CP_COMMIT(); CP_WAIT0(); __syncthreads();

    // hoist Q a-frags: 4 k16 (warp owns rows w*16..w*16+15)
    unsigned qa[4][4];
    #pragma unroll
    for (int j2=0; j2<4; j2++)
        ldsm4(qa[j2], sm2u(smh + (w*16 + arow)*72 + j2*16 + akh));

    float S[8][4];
    #pragma unroll
    for (int nf=0;nf<8;nf++){ S[nf][0]=S[nf][1]=S[nf][2]=S[nf][3]=0.f; }

    // QR = Q x r0^T
    #pragma unroll
    for (int j2=0; j2<4; j2++)
        #pragma unroll
        for (int p=0; p<4; p++){
            unsigned bbf[4];
            ldsm4(bbf, sm2u(smh + HVB(0) + (p*16 + brow)*72 + j2*16 + bkh));
            mma_f16(S[2*p],   qa[j2], bbf[0], bbf[1]);
            mma_f16(S[2*p+1], qa[j2], bbf[2], bbf[3]);
        }
    #pragma unroll
    for (int nf=0; nf<8; nf++){
        int c = nf*8 + 2*te;
        smf[MQRF + rw*65 + c]       = S[nf][0];
        smf[MQRF + rw*65 + c+1]     = S[nf][1];
        smf[MQRF + (rw+8)*65 + c]   = S[nf][2];
        smf[MQRF + (rw+8)*65 + c+1] = S[nf][3];
    }
    __syncthreads();

    // stage tile 0 (sum keys k2/v2) into buf 0
    stage_kv_h(smh, HKB(0), HVB(0),
               g_k2p + (size_t)bh*S_*64, g_v2t + (size_t)bh*64*S_, 64, t);
    CP_COMMIT();

    float O[8][4];
    #pragma unroll
    for (int nf=0;nf<8;nf++){ O[nf][0]=O[nf][1]=O[nf][2]=O[nf][3]=0.f; }
    float mr0 = -1e30f, mr1 = -1e30f, lr0 = 0.f, lr1 = 0.f;

    const unsigned char* igbase = g_idx8 + ((size_t)b*TOTLEN + S_ + q0)*R_;

    for (int kt = 0; kt < 33; kt++){
        if (kt < 32){
            int k0n = kt*64;
            int nb = (kt+1)&1;
            stage_kv_h(smh, HKB(nb), HVB(nb),
                       g_kp + ((size_t)bh*R_ + k0n)*64,
                       g_vt + (size_t)bh*64*R_ + k0n, R_, t);
            CP_COMMIT(); CP_WAIT1();
        } else {
            CP_WAIT0();
        }
        __syncthreads();
        int bu = kt&1;

        // idx prefetch (covered by QK mma latency)
        unsigned ix0[8], ix1[8];
        if (kt >= 1){
            const unsigned char* ig = igbase + (kt-1)*64;
            #pragma unroll
            for (int nf=0; nf<8; nf++){
                ix0[nf] = *(const unsigned short*)(ig + (size_t)rw*R_ + nf*8 + 2*te);
                ix1[nf] = *(const unsigned short*)(ig + (size_t)(rw+8)*R_ + nf*8 + 2*te);
            }
        }

        // QK
        #pragma unroll
        for (int nf=0;nf<8;nf++){ S[nf][0]=S[nf][1]=S[nf][2]=S[nf][3]=0.f; }
        #pragma unroll
        for (int j2=0; j2<4; j2++)
            #pragma unroll
            for (int p=0; p<4; p++){
                unsigned bbf[4];
                ldsm4(bbf, sm2u(smh + HKB(bu) + (p*16 + brow)*72 + j2*16 + bkh));
                mma_f16(S[2*p],   qa[j2], bbf[0], bbf[1]);
                mma_f16(S[2*p+1], qa[j2], bbf[2], bbf[3]);
            }

        // bias gather
        if (kt >= 1){
            #pragma unroll
            for (int nf=0; nf<8; nf++){
                S[nf][0] += smf[MQRF + rw*65 + (ix0[nf]&255)];
                S[nf][1] += smf[MQRF + rw*65 + (ix0[nf]>>8)];
                S[nf][2] += smf[MQRF + (rw+8)*65 + (ix1[nf]&255)];
                S[nf][3] += smf[MQRF + (rw+8)*65 + (ix1[nf]>>8)];
            }
        }

        // softmax (register state)
        float tm0 = -1e30f, tm1 = -1e30f;
        #pragma unroll
        for (int nf=0; nf<8; nf++){
            tm0 = fmaxf(tm0, fmaxf(S[nf][0], S[nf][1]));
            tm1 = fmaxf(tm1, fmaxf(S[nf][2], S[nf][3]));
        }
        tm0 = fmaxf(tm0, __shfl_xor_sync(0xffffffffu, tm0, 1));
        tm0 = fmaxf(tm0, __shfl_xor_sync(0xffffffffu, tm0, 2));
        tm1 = fmaxf(tm1, __shfl_xor_sync(0xffffffffu, tm1, 1));
        tm1 = fmaxf(tm1, __shfl_xor_sync(0xffffffffu, tm1, 2));
        float mn0 = fmaxf(mr0, tm0), mn1 = fmaxf(mr1, tm1);
        float f0 = __expf(mr0 - mn0), f1 = __expf(mr1 - mn1);
        mr0 = mn0; mr1 = mn1;
        float rs0 = 0.f, rs1 = 0.f;
        #pragma unroll
        for (int nf=0; nf<8; nf++){
            S[nf][0] = __expf(S[nf][0]-mn0); rs0 += S[nf][0];
            S[nf][1] = __expf(S[nf][1]-mn0); rs0 += S[nf][1];
            S[nf][2] = __expf(S[nf][2]-mn1); rs1 += S[nf][2];
            S[nf][3] = __expf(S[nf][3]-mn1); rs1 += S[nf][3];
        }
        rs0 += __shfl_xor_sync(0xffffffffu, rs0, 1);
        rs0 += __shfl_xor_sync(0xffffffffu, rs0, 2);
        rs1 += __shfl_xor_sync(0xffffffffu, rs1, 1);
        rs1 += __shfl_xor_sync(0xffffffffu, rs1, 2);
        lr0 = lr0*f0 + rs0; lr1 = lr1*f1 + rs1;
        #pragma unroll
        for (int nf=0; nf<8; nf++){
            O[nf][0]*=f0; O[nf][1]*=f0; O[nf][2]*=f1; O[nf][3]*=f1;
        }

        // PV: pack P c-frag -> a-frag directly (fp16)
        #pragma unroll
        for (int j2=0; j2<4; j2++){
            unsigned pa[4];
            pa[0] = packh2(S[2*j2][0],   S[2*j2][1]);
            pa[1] = packh2(S[2*j2][2],   S[2*j2][3]);
            pa[2] = packh2(S[2*j2+1][0], S[2*j2+1][1]);
            pa[3] = packh2(S[2*j2+1][2], S[2*j2+1][3]);
            #pragma unroll
            for (int pd=0; pd<4; pd++){
                unsigned bv[4];
                ldsm4(bv, sm2u(smh + HVB(bu) + (pd*16 + brow)*72 + j2*16 + bkh));
                mma_f16(O[2*pd],   pa, bv[0], bv[1]);
                mma_f16(O[2*pd+1], pa, bv[2], bv[3]);
            }
        }
        __syncthreads();
    }

    // output: fp16 into g_attnp
    {
        float inv0 = 1.f/lr0, inv1 = 1.f/lr1;
        int qg0 = q0 + rw;
        __half* dst0 = g_attnp + ((size_t)(qg0*B_ + b))*E_ + h*64;
        __half* dst1 = g_attnp + ((size_t)((qg0+8)*B_ + b))*E_ + h*64;
        #pragma unroll
        for (int nf=0; nf<8; nf++){
            int c = nf*8 + 2*te;
            *(unsigned*)&dst0[c] = packh2(O[nf][0]*inv0, O[nf][1]*inv0);
            *(unsigned*)&dst1[c] = packh2(O[nf][2]*inv1, O[nf][3]*inv1);
        }
    }
}

// ================= fp16 sum attention (split-K, 64q, R11) ===================
#define SKB(b) ((b)*4608)
#define SVB(b) (9216 + (b)*4608)
#define AQRF   9216
#define SUM_SMEM_BYTES (36864 + 64*68*4)   /* 54272 */

__global__ __launch_bounds__(128,2) void attn_sum_kernel(const int* __restrict__ tok,
        const float* __restrict__ emb_sum){
    extern __shared__ char smraw[];
    __half* smh = (__half*)smraw;
    float* smf = (float*)smraw;
    int t = threadIdx.x, lane = t & 31, w = t >> 5;
    int tq = lane >> 2, te = lane & 3;
    LDSM_OFFS();
    int bh = blockIdx.x, split = blockIdx.y;
    int b = bh >> 4, h = bh & 15;

    {
        int row = t>>1, halfc = (t&1)*32;
        int token = tok[b*S_ + row];
        const float4* p = (const float4*)(emb_sum + (size_t)token*E_ + h*64 + halfc);
        #pragma unroll
        for (int j=0;j<8;j++){
            float4 v = p[j]; int c = halfc + j*4;
            uint2 u; u.x = packh2(v.x*SCALE_, v.y*SCALE_);
            u.y = packh2(v.z*SCALE_, v.w*SCALE_);
            *(uint2*)&smh[row*72 + c] = u;
        }
        const __half* rg = g_r0p + (size_t)h*Z_*64;
        #pragma unroll
        for (int j=0;j<4;j++){
            int c = t + 128*j; int rr = c>>3, seg = c&7;
            cp16(smh + SVB(0) + rr*72 + seg*8, rg + (size_t)rr*64 + seg*8);
        }
    }
    CP_COMMIT(); CP_WAIT0(); __syncthreads();

    unsigned qa[4][4];
    #pragma unroll
    for (int j2=0; j2<4; j2++)
        ldsm4(qa[j2], sm2u(smh + (w*16 + arow)*72 + j2*16 + akh));

    float S[8][4];
    #pragma unroll
    for (int nf=0;nf<8;nf++){ S[nf][0]=S[nf][1]=S[nf][2]=S[nf][3]=0.f; }
    #pragma unroll
    for (int j2=0; j2<4; j2++)
        #pragma unroll
        for (int p=0; p<4; p++){
            unsigned bbf[4];
            ldsm4(bbf, sm2u(smh + SVB(0) + (p*16 + brow)*72 + j2*16 + bkh));
            mma_f16(S[2*p],   qa[j2], bbf[0], bbf[1]);
            mma_f16(S[2*p+1], qa[j2], bbf[2], bbf[3]);
        }
    #pragma unroll
    for (int nf=0; nf<8; nf++){
        int row = w*16 + tq, c = nf*8 + 2*te;
        smf[AQRF + row*68 + c]       = S[nf][0];
        smf[AQRF + row*68 + c+1]     = S[nf][1];
        smf[AQRF + (row+8)*68 + c]   = S[nf][2];
        smf[AQRF + (row+8)*68 + c+1] = S[nf][3];
    }
    __syncthreads();

    int kbase = split*256;
    {
        const __half* kg = g_kp + ((size_t)bh*R_ + kbase)*64;
        const __half* vg = g_vt + (size_t)bh*64*R_ + kbase;
        #pragma unroll
        for (int j=0;j<4;j++){
            int c = t + 128*j; int row = c>>3, seg = c&7;
            cp16(smh + SKB(0) + row*72 + seg*8, kg + (size_t)row*64 + seg*8);
            cp16(smh + SVB(0) + row*72 + seg*8, vg + (size_t)row*R_ + seg*8);
        }
    }
    CP_COMMIT();

    float O[8][4];
    #pragma unroll
    for (int nf=0;nf<8;nf++){ O[nf][0]=O[nf][1]=O[nf][2]=O[nf][3]=0.f; }
    float mr0 = -1e30f, mr1 = -1e30f, lr0 = 0.f, lr1 = 0.f;
    const unsigned char* igbase = g_idx8 + (size_t)b*TOTLEN*R_;

    for (int kt = 0; kt < 4; kt++){
        if (kt < 3){
            int k0n = kbase + (kt+1)*64;
            int nb = (kt+1)&1;
            const __half* kg = g_kp + ((size_t)bh*R_ + k0n)*64;
            const __half* vg = g_vt + (size_t)bh*64*R_ + k0n;
            #pragma unroll
            for (int j=0;j<4;j++){
                int c = t + 128*j; int row = c>>3, seg = c&7;
                cp16(smh + SKB(nb) + row*72 + seg*8, kg + (size_t)row*64 + seg*8);
                cp16(smh + SVB(nb) + row*72 + seg*8, vg + (size_t)row*R_ + seg*8);
            }
            CP_COMMIT(); CP_WAIT1();
        } else {
            CP_WAIT0();
        }
        __syncthreads();
        int bu = kt&1;

        unsigned ix0[8], ix1[8];
        {
            const unsigned char* ig = igbase + kbase + kt*64;
            #pragma unroll
            for (int nf=0; nf<8; nf++){
                int row = w*16 + tq;
                ix0[nf] = *(const unsigned short*)(ig + (size_t)row*R_ + nf*8 + 2*te);
                ix1[nf] = *(const unsigned short*)(ig + (size_t)(row+8)*R_ + nf*8 + 2*te);
            }
        }

        #pragma unroll
        for (int nf=0;nf<8;nf++){ S[nf][0]=S[nf][1]=S[nf][2]=S[nf][3]=0.f; }
        #pragma unroll
        for (int j2=0; j2<4; j2++)
            #pragma unroll
            for (int p=0; p<4; p++){
                unsigned bbf[4];
                ldsm4(bbf, sm2u(smh + SKB(bu) + (p*16 + brow)*72 + j2*16 + bkh));
                mma_f16(S[2*p],   qa[j2], bbf[0], bbf[1]);
                mma_f16(S[2*p+1], qa[j2], bbf[2], bbf[3]);
            }

        {
            int row = w*16 + tq;
            #pragma unroll
            for (int nf=0; nf<8; nf++){
                S[nf][0] += smf[AQRF + row*68 + (ix0[nf]&255)];
                S[nf][1] += smf[AQRF + row*68 + (ix0[nf]>>8)];
                S[nf][2] += smf[AQRF + (row+8)*68 + (ix1[nf]&255)];
                S[nf][3] += smf[AQRF + (row+8)*68 + (ix1[nf]>>8)];
            }
        }

        float tm0 = -1e30f, tm1 = -1e30f;
        #pragma unroll
        for (int nf=0; nf<8; nf++){
            tm0 = fmaxf(tm0, fmaxf(S[nf][0], S[nf][1]));
            tm1 = fmaxf(tm1, fmaxf(S[nf][2], S[nf][3]));
        }
        tm0 = fmaxf(tm0, __shfl_xor_sync(0xffffffffu, tm0, 1));
        tm0 = fmaxf(tm0, __shfl_xor_sync(0xffffffffu, tm0, 2));
        tm1 = fmaxf(tm1, __shfl_xor_sync(0xffffffffu, tm1, 1));
        tm1 = fmaxf(tm1, __shfl_xor_sync(0xffffffffu, tm1, 2));
        float mn0 = fmaxf(mr0, tm0), mn1 = fmaxf(mr1, tm1);
        float f0 = __expf(mr0 - mn0), f1 = __expf(mr1 - mn1);
        mr0 = mn0; mr1 = mn1;
        float rs0 = 0.f, rs1 = 0.f;
        #pragma unroll
        for (int nf=0; nf<8; nf++){
            S[nf][0] = __expf(S[nf][0]-mn0); rs0 += S[nf][0];
            S[nf][1] = __expf(S[nf][1]-mn0); rs0 += S[nf][1];
            S[nf][2] = __expf(S[nf][2]-mn1); rs1 += S[nf][2];
            S[nf][3] = __expf(S[nf][3]-mn1); rs1 += S[nf][3];
        }
        rs0 += __shfl_xor_sync(0xffffffffu, rs0, 1);
        rs0 += __shfl_xor_sync(0xffffffffu, rs0, 2);
        rs1 += __shfl_xor_sync(0xffffffffu, rs1, 1);
        rs1 += __shfl_xor_sync(0xffffffffu, rs1, 2);
        lr0 = lr0*f0 + rs0; lr1 = lr1*f1 + rs1;
        #pragma unroll
        for (int nf=0; nf<8; nf++){
            O[nf][0]*=f0; O[nf][1]*=f0; O[nf][2]*=f1; O[nf][3]*=f1;
        }
        #pragma unroll
        for (int j2=0; j2<4; j2++){
            unsigned pa[4];
            pa[0] = packh2(S[2*j2][0],   S[2*j2][1]);
            pa[1] = packh2(S[2*j2][2],   S[2*j2][3]);
            pa[2] = packh2(S[2*j2+1][0], S[2*j2+1][1]);
            pa[3] = packh2(S[2*j2+1][2], S[2*j2+1][3]);
            #pragma unroll
            for (int pd=0; pd<4; pd++){
                unsigned bv[4];
                ldsm4(bv, sm2u(smh + SVB(bu) + (pd*16 + brow)*72 + j2*16 + bkh));
                mma_f16(O[2*pd],   pa, bv[0], bv[1]);
                mma_f16(O[2*pd+1], pa, bv[2], bv[3]);
            }
        }
        __syncthreads();
    }

    int pb = bh*SPLITS + split;
    int s0 = w*16 + tq;
    #pragma unroll
    for (int nf=0; nf<8; nf++){
        int c = nf*8 + 2*te;
        *(float2*)&g_pacc[((size_t)pb*S_ + s0)*64 + c] =
            make_float2(O[nf][0], O[nf][1]);
        *(float2*)&g_pacc[((size_t)pb*S_ + s0 + 8)*64 + c] =
            make_float2(O[nf][2], O[nf][3]);
    }
    if (te == 0){
        g_pm[pb*S_ + s0] = mr0;    g_pm[pb*S_ + s0 + 8] = mr1;
        g_pl[pb*S_ + s0] = lr0;    g_pl[pb*S_ + s0 + 8] = lr1;
    }
}

// -------- combine split-K partials -> g_sumx2 -------------------------------
__global__ __launch_bounds__(64) void combine_kernel(){
    int rowq = blockIdx.x;
    int bh = rowq >> 6, s = rowq & 63;
    int d = threadIdx.x;
    float mv[SPLITS];
    float M = -1e30f;
    #pragma unroll
    for (int i=0;i<SPLITS;i++){
        mv[i] = g_pm[(bh*SPLITS + i)*S_ + s];
        M = fmaxf(M, mv[i]);
    }
    float L = 0.f, acc = 0.f;
    #pragma unroll
    for (int i=0;i<SPLITS;i++){
        float w = __expf(mv[i] - M);
        acc += w * g_pacc[((size_t)(bh*SPLITS + i)*S_ + s)*64 + d];
        L   += w * g_pl[(bh*SPLITS + i)*S_ + s];
    }
    g_sumx2[(bh*S_ + s)*64 + d] = acc / L;
}

// -------- per-row (b,h,s) projections sum_k2/sum_v2 with LN -> fp16 ---------
__global__ __launch_bounds__(64) void k2v2_kernel(const float* __restrict__ Wk2,
        const float* __restrict__ bk2, const float* __restrict__ Wv2,
        const float* __restrict__ bv2, const float* __restrict__ g1,
        const float* __restrict__ b1, const float* __restrict__ g2,
        const float* __restrict__ b2){
    __shared__ float xr[64];
    __shared__ float red[2];
    int row = blockIdx.x, t = threadIdx.x;
    int bh = row >> 6, s = row & 63;
    xr[t] = g_sumx2[row*64 + t];
    __syncthreads();
    #pragma unroll
    for (int pass=0; pass<2; pass++){
        const float* W  = pass ? Wv2 : Wk2;
        const float* bb = pass ? bv2 : bk2;
        const float* gg = pass ? g2  : g1;
        const float* bt = pass ? b2  : b1;
        float a = bb[t];
        #pragma unroll 8
        for (int j=0;j<64;j++) a += xr[j]*W[j*64+t];
        float sred = a;
        #pragma unroll
        for (int o=16;o;o>>=1) sred += __shfl_xor_sync(0xffffffffu, sred, o);
        if ((t&31)==0) red[t>>5] = sred;
        __syncthreads();
        float mean = (red[0]+red[1]) * (1.f/64.f);
        __syncthreads();
        float dv = a - mean;
        float v2 = dv*dv;
        #pragma unroll
        for (int o=16;o;o>>=1) v2 += __shfl_xor_sync(0xffffffffu, v2, o);
        if ((t&31)==0) red[t>>5] = v2;
        __syncthreads();
        float var = (red[0]+red[1]) * (1.f/64.f);
        __syncthreads();
        float outv = dv*rsqrtf(var+1e-5f)*gg[t] + bt[t];
        if (pass == 0)
            g_k2p[(size_t)row*64 + t] = __float2half_rn(outv);
        else
            g_v2t[((size_t)bh*64 + t)*64 + s] = __float2half_rn(outv);
    }
}

// ---------------------------------------------------------------------------
extern "C" void kernel_launch(void* const* d_in, const int* in_sizes, int n_in,
                              void* d_out, int out_size){
    const float* reg_x   = (const float*)d_in[0];
    const int*   tok     = (const int*)d_in[1];
    const int*   rel_idx = (const int*)d_in[2];
    const float* emb_sum  = (const float*)d_in[5];
    const float* rel_emb0 = (const float*)d_in[6];
    const float* Wq  = (const float*)d_in[7];  const float* bq  = (const float*)d_in[8];
    const float* Wk  = (const float*)d_in[9];  const float* bk  = (const float*)d_in[10];
    const float* Wv  = (const float*)d_in[11]; const float* bv  = (const float*)d_in[12];
    const float* Wr0 = (const float*)d_in[13]; const float* br0 = (const float*)d_in[14];
    const float* Wk2 = (const float*)d_in[15]; const float* bk2 = (const float*)d_in[16];
    const float* Wv2 = (const float*)d_in[17]; const float* bv2 = (const float*)d_in[18];
    const float* Wo  = (const float*)d_in[19]; const float* bo  = (const float*)d_in[20];
    const float* lnkg  = (const float*)d_in[21]; const float* lnkb  = (const float*)d_in[22];
    const float* lnvg  = (const float*)d_in[23]; const float* lnvb  = (const float*)d_in[24];
    const float* lnk2g = (const float*)d_in[25]; const float* lnk2b = (const float*)d_in[26];
    const float* lnv2g = (const float*)d_in[27]; const float* lnv2b = (const float*)d_in[28];
    float* out = (float*)d_out;

    cudaFuncSetAttribute(attn_sum_kernel,  cudaFuncAttributeMaxDynamicSharedMemorySize, SUM_SMEM_BYTES);
    cudaFuncSetAttribute(attn_main_kernel, cudaFuncAttributeMaxDynamicSharedMemorySize, MAIN_SMEM_BYTES);
    cudaFuncSetAttribute(gemm_fused, cudaFuncAttributeMaxDynamicSharedMemorySize, GEMM_SMEM_BYTES);

    __half *xp, *attnp, *wqp, *wkp, *wvp, *wop;
    cudaGetSymbolAddress((void**)&xp, g_xp);
    cudaGetSymbolAddress((void**)&attnp, g_attnp);
    cudaGetSymbolAddress((void**)&wqp, g_Wqp);
    cudaGetSymbolAddress((void**)&wkp, g_Wkp);
    cudaGetSymbolAddress((void**)&wvp, g_Wvp);
    cudaGetSymbolAddress((void**)&wop, g_Wop);

    dim3 wgrid(32,32);
    dim3 wblk(32,8);
    dim3 ggrid(E_/128, MROWS/128);   // (8, 32)

    // R11 launch order (capture = launch #4 -> gemm_fused)
    cvtA_kernel<<<MROWS*E_/4/256, 256>>>(reg_x, xp);                    // 1
    cvtW_kernel<<<wgrid, wblk>>>(Wk, wkp);                              // 2
    cvtW_kernel<<<wgrid, wblk>>>(Wv, wvp);                              // 3
    gemm_fused<<<ggrid, 256, GEMM_SMEM_BYTES>>>(xp, wkp, bk, (float*)0, 1, lnkg, lnkb); // 4
    gemm_fused<<<ggrid, 256, GEMM_SMEM_BYTES>>>(xp, wvp, bv, (float*)0, 2, lnvg, lnvb); // 5
    cvtW_kernel<<<wgrid, wblk>>>(Wq, wqp);                              // 6
    gemm_fused<<<ggrid, 256, GEMM_SMEM_BYTES>>>(xp, wqp, bq, (float*)0, 0, (const float*)0, (const float*)0); // 7
    r0_kernel<<<Z_*H_, 64>>>(rel_emb0, Wr0, br0);                       // 8
    idx8_kernel<<<(B_*TOTLEN*R_/4 + 255)/256, 256>>>(rel_idx);          // 9
    cvtW_kernel<<<wgrid, wblk>>>(Wo, wop);                              // 10

    attn_sum_kernel<<<dim3(B_*H_, SPLITS), 128, SUM_SMEM_BYTES>>>(tok, emb_sum);
    combine_kernel<<<B_*H_*S_, 64>>>();
    k2v2_kernel<<<B_*H_*S_, 64>>>(Wk2, bk2, Wv2, bv2, lnk2g, lnk2b, lnv2g, lnv2b);

    attn_main_kernel<<<dim3(R_/128, H_, B_), 256, MAIN_SMEM_BYTES>>>();

    gemm_fused<<<ggrid, 256, GEMM_SMEM_BYTES>>>(attnp, wop, bo, out, 3, (const float*)0, (const float*)0);
}

// round 16
// speedup vs baseline: 1.6066x; 1.6066x over previous
#include <cuda_runtime.h>
#include <cuda_fp16.h>
#include <math.h>

#define H_ 16
#define D_ 64
#define R_ 2048
#define S_ 64
#define B_ 2
#define E_ 1024
#define Z_ 64
#define SCALE_ 0.125f
#define MROWS (R_*B_)   /* 4096 */
#define SPLITS 8
#define TOTLEN (S_+R_)  /* 2112 */

// ---------------- scratch (device globals: allocation-free) ----------------
__device__ __half g_xp[MROWS*E_];
__device__ __half g_attnp[MROWS*E_];
__device__ __half g_Wqp[E_*E_];
__device__ __half g_Wkp[E_*E_];
__device__ __half g_Wvp[E_*E_];
__device__ __half g_Wop[E_*E_];
__device__ __half g_qp[B_*H_*R_*D_];
__device__ __half g_kp[B_*H_*R_*D_];
__device__ __half g_vt[B_*H_*D_*R_];
__device__ __half g_r0p[H_*Z_*D_];
__device__ __half g_k2p[B_*H_*S_*D_];
__device__ __half g_v2t[B_*H_*D_*S_];
__device__ unsigned char g_idx8[B_*TOTLEN*R_];
__device__ float g_sumx2[B_*H_*S_*D_];
__device__ float g_pacc[B_*H_*SPLITS*S_*D_];
__device__ float g_pm[B_*H_*SPLITS*S_];
__device__ float g_pl[B_*H_*SPLITS*S_];

// ---------------- helpers ---------------------------------------------------
__device__ __forceinline__ unsigned packh2(float lo, float hi){
    unsigned u;
    asm("{.reg .f16 l,h;\n cvt.rn.f16.f32 l,%1;\n cvt.rn.f16.f32 h,%2;\n mov.b32 %0,{l,h};}\n"
        : "=r"(u) : "f"(lo), "f"(hi));
    return u;
}
__device__ __forceinline__ unsigned sm2u(const void* p){
    return (unsigned)__cvta_generic_to_shared(p);
}
__device__ __forceinline__ void ldsm4(unsigned* r, unsigned addr){
    asm volatile("ldmatrix.sync.aligned.m8n8.x4.shared.b16 {%0,%1,%2,%3},[%4];"
        : "=r"(r[0]), "=r"(r[1]), "=r"(r[2]), "=r"(r[3]) : "r"(addr));
}
__device__ __forceinline__ void mma_f16(float* c, const unsigned* a,
        unsigned b0, unsigned b1){
    asm volatile(
        "mma.sync.aligned.m16n8k16.row.col.f32.f16.f16.f32 "
        "{%0,%1,%2,%3},{%4,%5,%6,%7},{%8,%9},{%0,%1,%2,%3};"
        : "+f"(c[0]), "+f"(c[1]), "+f"(c[2]), "+f"(c[3])
        : "r"(a[0]), "r"(a[1]), "r"(a[2]), "r"(a[3]), "r"(b0), "r"(b1));
}
__device__ __forceinline__ void cp16(void* dst, const void* src){
    unsigned d = (unsigned)__cvta_generic_to_shared(dst);
    asm volatile("cp.async.cg.shared.global [%0],[%1],16;" :: "r"(d), "l"(src));
}
#define CP_COMMIT() asm volatile("cp.async.commit_group;" ::: "memory")
#define CP_WAIT0()  asm volatile("cp.async.wait_group 0;" ::: "memory")
#define CP_WAIT1()  asm volatile("cp.async.wait_group 1;" ::: "memory")

#define LDSM_OFFS()                                                          \
    int arow = (lane&7) + ((lane>>3)&1)*8;                                   \
    int akh  = ((lane>>4)&1)*8;                                              \
    int brow = (lane&7) + ((lane>>4)&1)*8;                                   \
    int bkh  = ((lane>>3)&1)*8;

// -------- pre-conversion kernels -------------------------------------------
__global__ __launch_bounds__(256) void cvtA_kernel(const float* __restrict__ src,
        __half* __restrict__ dst){
    size_t i = (size_t)blockIdx.x*256 + threadIdx.x;
    size_t m = i >> 8; int kq = (int)(i & 255) * 4;
    float4 v = *(const float4*)(src + m*E_ + kq);
    uint2 u; u.x = packh2(v.x, v.y); u.y = packh2(v.z, v.w);
    *(uint2*)&dst[m*E_ + kq] = u;
}
// all four weights in one launch: blockIdx.z selects (W, out)
__global__ void cvtW_kernel(const float* __restrict__ W0, const float* __restrict__ W1,
        const float* __restrict__ W2, const float* __restrict__ W3){
    __shared__ float tile[32][33];
    const float* W; __half* out;
    switch (blockIdx.z){
        case 0: W = W0; out = g_Wqp; break;
        case 1: W = W1; out = g_Wkp; break;
        case 2: W = W2; out = g_Wvp; break;
        default: W = W3; out = g_Wop; break;
    }
    int k0 = blockIdx.y*32, n0 = blockIdx.x*32;
    int tx = threadIdx.x, ty = threadIdx.y;  // 32 x 8
    #pragma unroll
    for (int j=0;j<4;j++)
        tile[ty+8*j][tx] = W[(size_t)(k0+ty+8*j)*E_ + n0 + tx];
    __syncthreads();
    #pragma unroll
    for (int j=0;j<4;j++){
        int n = n0 + ty + 8*j;
        out[(size_t)n*E_ + k0 + tx] = __float2half_rn(tile[tx][ty+8*j]);
    }
}

// ---------------- fp16 GEMM + fused epilogue (3-stage pipeline, R11) --------
#define GSTG 10240
#define GEMM_SMEM_BYTES (3*GSTG*2)   /* 61440 */

__device__ __forceinline__ void g_stage_h(__half* smh, int s,
        const __half* Ag, const __half* Wg, int t){
    __half* base = smh + s*GSTG;
    #pragma unroll
    for (int j=0;j<2;j++){
        int c = t + 256*j; int row = c>>2, seg = c&3;   // 128 rows x 4 segs (BK=32)
        cp16(base + row*40 + seg*8, Ag + (size_t)row*E_ + seg*8);
        cp16(base + 5120 + row*40 + seg*8, Wg + (size_t)row*E_ + seg*8);
    }
}

__global__ __launch_bounds__(256) void gemm_fused(const __half* __restrict__ A,
        const __half* __restrict__ W, const float* __restrict__ bias,
        float* __restrict__ outF, int mode,
        const float* __restrict__ gg, const float* __restrict__ bb){
    extern __shared__ __half smh[];
    int t = threadIdx.x, lane = t & 31, w = t >> 5;
    int wm = w >> 1, wn = w & 1;
    int tq = lane >> 2, te = lane & 3;
    LDSM_OFFS();
    int row0 = blockIdx.y * 128, n0 = blockIdx.x * 128;
    const __half* Abase = A + (size_t)row0*E_;
    const __half* Wbase = W + (size_t)n0*E_;

    float acc[2][8][4];
    #pragma unroll
    for (int m=0;m<2;m++)
        #pragma unroll
        for (int n=0;n<8;n++)
            #pragma unroll
            for (int j=0;j<4;j++) acc[m][n][j]=0.f;

    g_stage_h(smh, 0, Abase, Wbase, t); CP_COMMIT();
    g_stage_h(smh, 1, Abase + 32, Wbase + 32, t); CP_COMMIT();

    for (int it=0; it<32; it++){
        if (it < 31){ CP_WAIT1(); } else { CP_WAIT0(); }
        __syncthreads();
        if (it + 2 < 32){
            g_stage_h(smh, (it+2)%3, Abase + (it+2)*32, Wbase + (it+2)*32, t);
            CP_COMMIT();
        }
        __half* As = smh + (it%3)*GSTG;
        __half* Bs = As + 5120;
        #pragma unroll
        for (int ks2=0; ks2<2; ks2++){
            int k0 = ks2*16;
            unsigned a[2][4];
            ldsm4(a[0], sm2u(As + (wm*32 +      arow)*40 + k0 + akh));
            ldsm4(a[1], sm2u(As + (wm*32 + 16 + arow)*40 + k0 + akh));
            #pragma unroll
            for (int p=0; p<4; p++){
                unsigned bbf[4];
                ldsm4(bbf, sm2u(Bs + (wn*64 + p*16 + brow)*40 + k0 + bkh));
                mma_f16(acc[0][2*p],   a[0], bbf[0], bbf[1]);
                mma_f16(acc[0][2*p+1], a[0], bbf[2], bbf[3]);
                mma_f16(acc[1][2*p],   a[1], bbf[0], bbf[1]);
                mma_f16(acc[1][2*p+1], a[1], bbf[2], bbf[3]);
            }
        }
        __syncthreads();
    }

    int h = blockIdx.x*2 + wn;
    #pragma unroll
    for (int mf=0; mf<2; mf++){
        #pragma unroll
        for (int rsel=0; rsel<2; rsel++){
            int m = row0 + wm*32 + mf*16 + tq + rsel*8;
            float v[16];
            #pragma unroll
            for (int nf=0; nf<8; nf++){
                int c = nf*8 + 2*te;
                v[2*nf]   = acc[mf][nf][2*rsel]   + __ldg(&bias[h*64 + c]);
                v[2*nf+1] = acc[mf][nf][2*rsel+1] + __ldg(&bias[h*64 + c + 1]);
            }
            if (mode == 3){
                #pragma unroll
                for (int nf=0; nf<8; nf++)
                    *(float2*)&outF[(size_t)m*E_ + h*64 + nf*8 + 2*te] =
                        make_float2(v[2*nf], v[2*nf+1]);
            } else if (mode == 0){
                int r = m>>1, b = m&1, bh = b*H_ + h;
                __half* dst = g_qp + ((size_t)bh*R_ + r)*64;
                #pragma unroll
                for (int nf=0; nf<8; nf++){
                    int c = nf*8 + 2*te;
                    *(unsigned*)&dst[c] = packh2(v[2*nf]*SCALE_, v[2*nf+1]*SCALE_);
                }
            } else {
                int r = m>>1, b = m&1, bh = b*H_ + h;
                float s = 0.f;
                #pragma unroll
                for (int i=0;i<16;i++) s += v[i];
                s += __shfl_xor_sync(0xffffffffu, s, 1);
                s += __shfl_xor_sync(0xffffffffu, s, 2);
                float mean = s*(1.f/64.f);
                float var = 0.f;
                #pragma unroll
                for (int i=0;i<16;i++){ float d = v[i]-mean; var += d*d; }
                var += __shfl_xor_sync(0xffffffffu, var, 1);
                var += __shfl_xor_sync(0xffffffffu, var, 2);
                float scl = rsqrtf(var*(1.f/64.f) + 1e-5f);
                if (mode == 1){
                    __half* dst = g_kp + ((size_t)bh*R_ + r)*64;
                    #pragma unroll
                    for (int nf=0; nf<8; nf++){
                        int c = nf*8 + 2*te;
                        *(unsigned*)&dst[c] = packh2(
                            (v[2*nf]-mean)*scl*__ldg(&gg[c]) + __ldg(&bb[c]),
                            (v[2*nf+1]-mean)*scl*__ldg(&gg[c+1]) + __ldg(&bb[c+1]));
                    }
                } else {
                    #pragma unroll
                    for (int nf=0; nf<8; nf++){
                        int c = nf*8 + 2*te;
                        g_vt[((size_t)bh*64 + c)*R_ + r] = __float2half_rn(
                            (v[2*nf]-mean)*scl*__ldg(&gg[c]) + __ldg(&bb[c]));
                        g_vt[((size_t)bh*64 + c+1)*R_ + r] = __float2half_rn(
                            (v[2*nf+1]-mean)*scl*__ldg(&gg[c+1]) + __ldg(&bb[c+1]));
                    }
                }
            }
        }
    }
}

// -------- r0p[h][z][d] = fp16( rel_emb0@Wr0 + br0 ) -------------------------
__global__ __launch_bounds__(64) void r0_kernel(const float* __restrict__ rel_emb0,
        const float* __restrict__ Wr0, const float* __restrict__ br0){
    int z = blockIdx.x >> 4, h = blockIdx.x & 15;
    int d = threadIdx.x;
    float a = br0[h*64+d];
    #pragma unroll 8
    for (int c=0;c<64;c++) a += rel_emb0[z*64+c]*Wr0[c*E_ + h*64 + d];
    g_r0p[(h*Z_ + z)*64 + d] = __float2half_rn(a);
}

// -------- compress rel_idx (int32 < 64) to u8 -------------------------------
__global__ __launch_bounds__(256) void idx8_kernel(const int* __restrict__ rel){
    size_t i = (size_t)blockIdx.x*256 + threadIdx.x;
    int4 v = ((const int4*)rel)[i];
    uchar4 u; u.x=(unsigned char)v.x; u.y=(unsigned char)v.y;
    u.z=(unsigned char)v.z; u.w=(unsigned char)v.w;
    ((uchar4*)g_idx8)[i] = u;
}

// ================= fp16 main attention: 128q/CTA, 4 warps (R11) =============
#define HKB(b) ((b)*4608)
#define HVB(b) (9216 + (b)*4608)
#define MQRF   9216
#define MAIN_SMEM_BYTES (36864 + 128*65*4)   /* 70144 */

// 128-thread staging: K/V tiles are 512 chunks each -> j<4
__device__ __forceinline__ void stage_kv_h(__half* smh, int kbo, int vbo,
        const __half* kg, const __half* vg, size_t vstride, int t){
    #pragma unroll
    for (int j=0;j<4;j++){
        int c = t + 128*j; int row = c>>3, seg = c&7;
        cp16(smh + kbo + row*72 + seg*8, kg + (size_t)row*64 + seg*8);
        cp16(smh + vbo + row*72 + seg*8, vg + (size_t)row*vstride + seg*8);
    }
}

__global__ __launch_bounds__(128,2) void attn_main_kernel(){
    extern __shared__ char smraw[];
    __half* smh = (__half*)smraw;
    float* smf = (float*)smraw;
    int t = threadIdx.x, lane = t & 31, w = t >> 5;
    int tq = lane >> 2, te = lane & 3;
    LDSM_OFFS();
    int b = blockIdx.z, h = blockIdx.y, bh = b*H_ + h;
    int q0 = blockIdx.x * 128;
    int r0w = w*32 + tq;

    {   // Q: 128 rows x 64 halves = 1024 cp16; r0: 64x64 = 512 cp16
        const __half* qg = g_qp + ((size_t)bh*R_ + q0)*64;
        const __half* rg = g_r0p + (size_t)h*Z_*64;
        #pragma unroll
        for (int j=0;j<8;j++){
            int c = t + 128*j; int row = c>>3, seg = c&7;
            cp16(smh + row*72 + seg*8, qg + (size_t)row*64 + seg*8);
        }
        #pragma unroll
        for (int j=0;j<4;j++){
            int c = t + 128*j; int row = c>>3, seg = c&7;
            cp16(smh + HVB(0) + row*72 + seg*8, rg + (size_t)row*64 + seg*8);
        }
    }
    CP_COMMIT(); CP_WAIT0(); __syncthreads();

    // hoist Q a-frags: 2 mf x 4 k16
    unsigned qa[2][4][4];
    #pragma unroll
    for (int mf=0; mf<2; mf++)
        #pragma unroll
        for (int j2=0; j2<4; j2++)
            ldsm4(qa[mf][j2], sm2u(smh + (w*32 + mf*16 + arow)*72 + j2*16 + akh));

    float S[2][8][4];
    #pragma unroll
    for (int mf=0;mf<2;mf++)
        #pragma unroll
        for (int nf=0;nf<8;nf++){ S[mf][nf][0]=S[mf][nf][1]=S[mf][nf][2]=S[mf][nf][3]=0.f; }

    // QR = Q x r0^T
    #pragma unroll
    for (int j2=0; j2<4; j2++)
        #pragma unroll
        for (int p=0; p<4; p++){
            unsigned bbf[4];
            ldsm4(bbf, sm2u(smh + HVB(0) + (p*16 + brow)*72 + j2*16 + bkh));
            mma_f16(S[0][2*p],   qa[0][j2], bbf[0], bbf[1]);
            mma_f16(S[0][2*p+1], qa[0][j2], bbf[2], bbf[3]);
            mma_f16(S[1][2*p],   qa[1][j2], bbf[0], bbf[1]);
            mma_f16(S[1][2*p+1], qa[1][j2], bbf[2], bbf[3]);
        }
    #pragma unroll
    for (int mf=0; mf<2; mf++)
        #pragma unroll
        for (int nf=0; nf<8; nf++){
            int row = r0w + mf*16, c = nf*8 + 2*te;
            smf[MQRF + row*65 + c]       = S[mf][nf][0];
            smf[MQRF + row*65 + c+1]     = S[mf][nf][1];
            smf[MQRF + (row+8)*65 + c]   = S[mf][nf][2];
            smf[MQRF + (row+8)*65 + c+1] = S[mf][nf][3];
        }
    __syncthreads();

    stage_kv_h(smh, HKB(0), HVB(0),
               g_k2p + (size_t)bh*S_*64, g_v2t + (size_t)bh*64*S_, 64, t);
    CP_COMMIT();

    float O[2][8][4];
    #pragma unroll
    for (int mf=0;mf<2;mf++)
        #pragma unroll
        for (int nf=0;nf<8;nf++){ O[mf][nf][0]=O[mf][nf][1]=O[mf][nf][2]=O[mf][nf][3]=0.f; }
    float mr[2][2], lr[2][2];
    #pragma unroll
    for (int mf=0;mf<2;mf++){ mr[mf][0]=mr[mf][1]=-1e30f; lr[mf][0]=lr[mf][1]=0.f; }

    const unsigned char* igbase = g_idx8 + ((size_t)b*TOTLEN + S_ + q0)*R_;

    for (int kt = 0; kt < 33; kt++){
        if (kt < 32){
            int k0n = kt*64;
            int nb = (kt+1)&1;
            stage_kv_h(smh, HKB(nb), HVB(nb),
                       g_kp + ((size_t)bh*R_ + k0n)*64,
                       g_vt + (size_t)bh*64*R_ + k0n, R_, t);
            CP_COMMIT(); CP_WAIT1();
        } else {
            CP_WAIT0();
        }
        __syncthreads();
        int bu = kt&1;

        unsigned ix0[2][8], ix1[2][8];
        if (kt >= 1){
            const unsigned char* ig = igbase + (kt-1)*64;
            #pragma unroll
            for (int mf=0; mf<2; mf++)
                #pragma unroll
                for (int nf=0; nf<8; nf++){
                    int row = r0w + mf*16;
                    ix0[mf][nf] = *(const unsigned short*)(ig + (size_t)row*R_ + nf*8 + 2*te);
                    ix1[mf][nf] = *(const unsigned short*)(ig + (size_t)(row+8)*R_ + nf*8 + 2*te);
                }
        }

        #pragma unroll
        for (int mf=0;mf<2;mf++)
            #pragma unroll
            for (int nf=0;nf<8;nf++){ S[mf][nf][0]=S[mf][nf][1]=S[mf][nf][2]=S[mf][nf][3]=0.f; }
        #pragma unroll
        for (int j2=0; j2<4; j2++)
            #pragma unroll
            for (int p=0; p<4; p++){
                unsigned bbf[4];
                ldsm4(bbf, sm2u(smh + HKB(bu) + (p*16 + brow)*72 + j2*16 + bkh));
                mma_f16(S[0][2*p],   qa[0][j2], bbf[0], bbf[1]);
                mma_f16(S[0][2*p+1], qa[0][j2], bbf[2], bbf[3]);
                mma_f16(S[1][2*p],   qa[1][j2], bbf[0], bbf[1]);
                mma_f16(S[1][2*p+1], qa[1][j2], bbf[2], bbf[3]);
            }

        if (kt >= 1){
            #pragma unroll
            for (int mf=0; mf<2; mf++)
                #pragma unroll
                for (int nf=0; nf<8; nf++){
                    int row = r0w + mf*16;
                    S[mf][nf][0] += smf[MQRF + row*65 + (ix0[mf][nf]&255)];
                    S[mf][nf][1] += smf[MQRF + row*65 + (ix0[mf][nf]>>8)];
                    S[mf][nf][2] += smf[MQRF + (row+8)*65 + (ix1[mf][nf]&255)];
                    S[mf][nf][3] += smf[MQRF + (row+8)*65 + (ix1[mf][nf]>>8)];
                }
        }

        #pragma unroll
        for (int mf=0; mf<2; mf++){
            float tm0 = -1e30f, tm1 = -1e30f;
            #pragma unroll
            for (int nf=0; nf<8; nf++){
                tm0 = fmaxf(tm0, fmaxf(S[mf][nf][0], S[mf][nf][1]));
                tm1 = fmaxf(tm1, fmaxf(S[mf][nf][2], S[mf][nf][3]));
            }
            tm0 = fmaxf(tm0, __shfl_xor_sync(0xffffffffu, tm0, 1));
            tm0 = fmaxf(tm0, __shfl_xor_sync(0xffffffffu, tm0, 2));
            tm1 = fmaxf(tm1, __shfl_xor_sync(0xffffffffu, tm1, 1));
            tm1 = fmaxf(tm1, __shfl_xor_sync(0xffffffffu, tm1, 2));
            float mn0 = fmaxf(mr[mf][0], tm0), mn1 = fmaxf(mr[mf][1], tm1);
            float f0 = __expf(mr[mf][0] - mn0), f1 = __expf(mr[mf][1] - mn1);
            mr[mf][0] = mn0; mr[mf][1] = mn1;
            float rs0 = 0.f, rs1 = 0.f;
            #pragma unroll
            for (int nf=0; nf<8; nf++){
                S[mf][nf][0] = __expf(S[mf][nf][0]-mn0); rs0 += S[mf][nf][0];
                S[mf][nf][1] = __expf(S[mf][nf][1]-mn0); rs0 += S[mf][nf][1];
                S[mf][nf][2] = __expf(S[mf][nf][2]-mn1); rs1 += S[mf][nf][2];
                S[mf][nf][3] = __expf(S[mf][nf][3]-mn1); rs1 += S[mf][nf][3];
            }
            rs0 += __shfl_xor_sync(0xffffffffu, rs0, 1);
            rs0 += __shfl_xor_sync(0xffffffffu, rs0, 2);
            rs1 += __shfl_xor_sync(0xffffffffu, rs1, 1);
            rs1 += __shfl_xor_sync(0xffffffffu, rs1, 2);
            lr[mf][0] = lr[mf][0]*f0 + rs0;
            lr[mf][1] = lr[mf][1]*f1 + rs1;
            #pragma unroll
            for (int nf=0; nf<8; nf++){
                O[mf][nf][0]*=f0; O[mf][nf][1]*=f0;
                O[mf][nf][2]*=f1; O[mf][nf][3]*=f1;
            }
        }

        #pragma unroll
        for (int j2=0; j2<4; j2++){
            unsigned pa[2][4];
            #pragma unroll
            for (int mf=0; mf<2; mf++){
                pa[mf][0] = packh2(S[mf][2*j2][0],   S[mf][2*j2][1]);
                pa[mf][1] = packh2(S[mf][2*j2][2],   S[mf][2*j2][3]);
                pa[mf][2] = packh2(S[mf][2*j2+1][0], S[mf][2*j2+1][1]);
                pa[mf][3] = packh2(S[mf][2*j2+1][2], S[mf][2*j2+1][3]);
            }
            #pragma unroll
            for (int pd=0; pd<4; pd++){
                unsigned bv[4];
                ldsm4(bv, sm2u(smh + HVB(bu) + (pd*16 + brow)*72 + j2*16 + bkh));
                mma_f16(O[0][2*pd],   pa[0], bv[0], bv[1]);
                mma_f16(O[0][2*pd+1], pa[0], bv[2], bv[3]);
                mma_f16(O[1][2*pd],   pa[1], bv[0], bv[1]);
                mma_f16(O[1][2*pd+1], pa[1], bv[2], bv[3]);
            }
        }
        __syncthreads();
    }

    #pragma unroll
    for (int mf=0; mf<2; mf++){
        float inv0 = 1.f/lr[mf][0], inv1 = 1.f/lr[mf][1];
        int qg0 = q0 + r0w + mf*16;
        __half* dst0 = g_attnp + ((size_t)(qg0*B_ + b))*E_ + h*64;
        __half* dst1 = g_attnp + ((size_t)((qg0+8)*B_ + b))*E_ + h*64;
        #pragma unroll
        for (int nf=0; nf<8; nf++){
            int c = nf*8 + 2*te;
            *(unsigned*)&dst0[c] = packh2(O[mf][nf][0]*inv0, O[mf][nf][1]*inv0);
            *(unsigned*)&dst1[c] = packh2(O[mf][nf][2]*inv1, O[mf][nf][3]*inv1);
        }
    }
}

// ================= fp16 sum attention (split-K, 64q, R11) ===================
#define SKB(b) ((b)*4608)
#define SVB(b) (9216 + (b)*4608)
#define AQRF   9216
#define SUM_SMEM_BYTES (36864 + 64*68*4)   /* 54272 */

__global__ __launch_bounds__(128,2) void attn_sum_kernel(const int* __restrict__ tok,
        const float* __restrict__ emb_sum){
    extern __shared__ char smraw[];
    __half* smh = (__half*)smraw;
    float* smf = (float*)smraw;
    int t = threadIdx.x, lane = t & 31, w = t >> 5;
    int tq = lane >> 2, te = lane & 3;
    LDSM_OFFS();
    int bh = blockIdx.x, split = blockIdx.y;
    int b = bh >> 4, h = bh & 15;

    {
        int row = t>>1, halfc = (t&1)*32;
        int token = tok[b*S_ + row];
        const float4* p = (const float4*)(emb_sum + (size_t)token*E_ + h*64 + halfc);
        #pragma unroll
        for (int j=0;j<8;j++){
            float4 v = p[j]; int c = halfc + j*4;
            uint2 u; u.x = packh2(v.x*SCALE_, v.y*SCALE_);
            u.y = packh2(v.z*SCALE_, v.w*SCALE_);
            *(uint2*)&smh[row*72 + c] = u;
        }
        const __half* rg = g_r0p + (size_t)h*Z_*64;
        #pragma unroll
        for (int j=0;j<4;j++){
            int c = t + 128*j; int rr = c>>3, seg = c&7;
            cp16(smh + SVB(0) + rr*72 + seg*8, rg + (size_t)rr*64 + seg*8);
        }
    }
    CP_COMMIT(); CP_WAIT0(); __syncthreads();

    unsigned qa[4][4];
    #pragma unroll
    for (int j2=0; j2<4; j2++)
        ldsm4(qa[j2], sm2u(smh + (w*16 + arow)*72 + j2*16 + akh));

    float S[8][4];
    #pragma unroll
    for (int nf=0;nf<8;nf++){ S[nf][0]=S[nf][1]=S[nf][2]=S[nf][3]=0.f; }
    #pragma unroll
    for (int j2=0; j2<4; j2++)
        #pragma unroll
        for (int p=0; p<4; p++){
            unsigned bbf[4];
            ldsm4(bbf, sm2u(smh + SVB(0) + (p*16 + brow)*72 + j2*16 + bkh));
            mma_f16(S[2*p],   qa[j2], bbf[0], bbf[1]);
            mma_f16(S[2*p+1], qa[j2], bbf[2], bbf[3]);
        }
    #pragma unroll
    for (int nf=0; nf<8; nf++){
        int row = w*16 + tq, c = nf*8 + 2*te;
        smf[AQRF + row*68 + c]       = S[nf][0];
        smf[AQRF + row*68 + c+1]     = S[nf][1];
        smf[AQRF + (row+8)*68 + c]   = S[nf][2];
        smf[AQRF + (row+8)*68 + c+1] = S[nf][3];
    }
    __syncthreads();

    int kbase = split*256;
    {
        const __half* kg = g_kp + ((size_t)bh*R_ + kbase)*64;
        const __half* vg = g_vt + (size_t)bh*64*R_ + kbase;
        #pragma unroll
        for (int j=0;j<4;j++){
            int c = t + 128*j; int row = c>>3, seg = c&7;
            cp16(smh + SKB(0) + row*72 + seg*8, kg + (size_t)row*64 + seg*8);
            cp16(smh + SVB(0) + row*72 + seg*8, vg + (size_t)row*R_ + seg*8);
        }
    }
    CP_COMMIT();

    float O[8][4];
    #pragma unroll
    for (int nf=0;nf<8;nf++){ O[nf][0]=O[nf][1]=O[nf][2]=O[nf][3]=0.f; }
    float mr0 = -1e30f, mr1 = -1e30f, lr0 = 0.f, lr1 = 0.f;
    const unsigned char* igbase = g_idx8 + (size_t)b*TOTLEN*R_;

    for (int kt = 0; kt < 4; kt++){
        if (kt < 3){
            int k0n = kbase + (kt+1)*64;
            int nb = (kt+1)&1;
            const __half* kg = g_kp + ((size_t)bh*R_ + k0n)*64;
            const __half* vg = g_vt + (size_t)bh*64*R_ + k0n;
            #pragma unroll
            for (int j=0;j<4;j++){
                int c = t + 128*j; int row = c>>3, seg = c&7;
                cp16(smh + SKB(nb) + row*72 + seg*8, kg + (size_t)row*64 + seg*8);
                cp16(smh + SVB(nb) + row*72 + seg*8, vg + (size_t)row*R_ + seg*8);
            }
            CP_COMMIT(); CP_WAIT1();
        } else {
            CP_WAIT0();
        }
        __syncthreads();
        int bu = kt&1;

        unsigned ix0[8], ix1[8];
        {
            const unsigned char* ig = igbase + kbase + kt*64;
            #pragma unroll
            for (int nf=0; nf<8; nf++){
                int row = w*16 + tq;
                ix0[nf] = *(const unsigned short*)(ig + (size_t)row*R_ + nf*8 + 2*te);
                ix1[nf] = *(const unsigned short*)(ig + (size_t)(row+8)*R_ + nf*8 + 2*te);
            }
        }

        #pragma unroll
        for (int nf=0;nf<8;nf++){ S[nf][0]=S[nf][1]=S[nf][2]=S[nf][3]=0.f; }
        #pragma unroll
        for (int j2=0; j2<4; j2++)
            #pragma unroll
            for (int p=0; p<4; p++){
                unsigned bbf[4];
                ldsm4(bbf, sm2u(smh + SKB(bu) + (p*16 + brow)*72 + j2*16 + bkh));
                mma_f16(S[2*p],   qa[j2], bbf[0], bbf[1]);
                mma_f16(S[2*p+1], qa[j2], bbf[2], bbf[3]);
            }

        {
            int row = w*16 + tq;
            #pragma unroll
            for (int nf=0; nf<8; nf++){
                S[nf][0] += smf[AQRF + row*68 + (ix0[nf]&255)];
                S[nf][1] += smf[AQRF + row*68 + (ix0[nf]>>8)];
                S[nf][2] += smf[AQRF + (row+8)*68 + (ix1[nf]&255)];
                S[nf][3] += smf[AQRF + (row+8)*68 + (ix1[nf]>>8)];
            }
        }

        float tm0 = -1e30f, tm1 = -1e30f;
        #pragma unroll
        for (int nf=0; nf<8; nf++){
            tm0 = fmaxf(tm0, fmaxf(S[nf][0], S[nf][1]));
            tm1 = fmaxf(tm1, fmaxf(S[nf][2], S[nf][3]));
        }
        tm0 = fmaxf(tm0, __shfl_xor_sync(0xffffffffu, tm0, 1));
        tm0 = fmaxf(tm0, __shfl_xor_sync(0xffffffffu, tm0, 2));
        tm1 = fmaxf(tm1, __shfl_xor_sync(0xffffffffu, tm1, 1));
        tm1 = fmaxf(tm1, __shfl_xor_sync(0xffffffffu, tm1, 2));
        float mn0 = fmaxf(mr0, tm0), mn1 = fmaxf(mr1, tm1);
        float f0 = __expf(mr0 - mn0), f1 = __expf(mr1 - mn1);
        mr0 = mn0; mr1 = mn1;
        float rs0 = 0.f, rs1 = 0.f;
        #pragma unroll
        for (int nf=0; nf<8; nf++){
            S[nf][0] = __expf(S[nf][0]-mn0); rs0 += S[nf][0];
            S[nf][1] = __expf(S[nf][1]-mn0); rs0 += S[nf][1];
            S[nf][2] = __expf(S[nf][2]-mn1); rs1 += S[nf][2];
            S[nf][3] = __expf(S[nf][3]-mn1); rs1 += S[nf][3];
        }
        rs0 += __shfl_xor_sync(0xffffffffu, rs0, 1);
        rs0 += __shfl_xor_sync(0xffffffffu, rs0, 2);
        rs1 += __shfl_xor_sync(0xffffffffu, rs1, 1);
        rs1 += __shfl_xor_sync(0xffffffffu, rs1, 2);
        lr0 = lr0*f0 + rs0; lr1 = lr1*f1 + rs1;
        #pragma unroll
        for (int nf=0; nf<8; nf++){
            O[nf][0]*=f0; O[nf][1]*=f0; O[nf][2]*=f1; O[nf][3]*=f1;
        }
        #pragma unroll
        for (int j2=0; j2<4; j2++){
            unsigned pa[4];
            pa[0] = packh2(S[2*j2][0],   S[2*j2][1]);
            pa[1] = packh2(S[2*j2][2],   S[2*j2][3]);
            pa[2] = packh2(S[2*j2+1][0], S[2*j2+1][1]);
            pa[3] = packh2(S[2*j2+1][2], S[2*j2+1][3]);
            #pragma unroll
            for (int pd=0; pd<4; pd++){
                unsigned bv[4];
                ldsm4(bv, sm2u(smh + SVB(bu) + (pd*16 + brow)*72 + j2*16 + bkh));
                mma_f16(O[2*pd],   pa, bv[0], bv[1]);
                mma_f16(O[2*pd+1], pa, bv[2], bv[3]);
            }
        }
        __syncthreads();
    }

    int pb = bh*SPLITS + split;
    int s0 = w*16 + tq;
    #pragma unroll
    for (int nf=0; nf<8; nf++){
        int c = nf*8 + 2*te;
        *(float2*)&g_pacc[((size_t)pb*S_ + s0)*64 + c] =
            make_float2(O[nf][0], O[nf][1]);
        *(float2*)&g_pacc[((size_t)pb*S_ + s0 + 8)*64 + c] =
            make_float2(O[nf][2], O[nf][3]);
    }
    if (te == 0){
        g_pm[pb*S_ + s0] = mr0;    g_pm[pb*S_ + s0 + 8] = mr1;
        g_pl[pb*S_ + s0] = lr0;    g_pl[pb*S_ + s0 + 8] = lr1;
    }
}

// -------- combine split-K partials -> g_sumx2 -------------------------------
__global__ __launch_bounds__(64) void combine_kernel(){
    int rowq = blockIdx.x;
    int bh = rowq >> 6, s = rowq & 63;
    int d = threadIdx.x;
    float mv[SPLITS];
    float M = -1e30f;
    #pragma unroll
    for (int i=0;i<SPLITS;i++){
        mv[i] = g_pm[(bh*SPLITS + i)*S_ + s];
        M = fmaxf(M, mv[i]);
    }
    float L = 0.f, acc = 0.f;
    #pragma unroll
    for (int i=0;i<SPLITS;i++){
        float w = __expf(mv[i] - M);
        acc += w * g_pacc[((size_t)(bh*SPLITS + i)*S_ + s)*64 + d];
        L   += w * g_pl[(bh*SPLITS + i)*S_ + s];
    }
    g_sumx2[(bh*S_ + s)*64 + d] = acc / L;
}

// -------- per-row (b,h,s) projections sum_k2/sum_v2 with LN -> fp16 ---------
__global__ __launch_bounds__(64) void k2v2_kernel(const float* __restrict__ Wk2,
        const float* __restrict__ bk2, const float* __restrict__ Wv2,
        const float* __restrict__ bv2, const float* __restrict__ g1,
        const float* __restrict__ b1, const float* __restrict__ g2,
        const float* __restrict__ b2){
    __shared__ float xr[64];
    __shared__ float red[2];
    int row = blockIdx.x, t = threadIdx.x;
    int bh = row >> 6, s = row & 63;
    xr[t] = g_sumx2[row*64 + t];
    __syncthreads();
    #pragma unroll
    for (int pass=0; pass<2; pass++){
        const float* W  = pass ? Wv2 : Wk2;
        const float* bb = pass ? bv2 : bk2;
        const float* gg = pass ? g2  : g1;
        const float* bt = pass ? b2  : b1;
        float a = bb[t];
        #pragma unroll 8
        for (int j=0;j<64;j++) a += xr[j]*W[j*64+t];
        float sred = a;
        #pragma unroll
        for (int o=16;o;o>>=1) sred += __shfl_xor_sync(0xffffffffu, sred, o);
        if ((t&31)==0) red[t>>5] = sred;
        __syncthreads();
        float mean = (red[0]+red[1]) * (1.f/64.f);
        __syncthreads();
        float dv = a - mean;
        float v2 = dv*dv;
        #pragma unroll
        for (int o=16;o;o>>=1) v2 += __shfl_xor_sync(0xffffffffu, v2, o);
        if ((t&31)==0) red[t>>5] = v2;
        __syncthreads();
        float var = (red[0]+red[1]) * (1.f/64.f);
        __syncthreads();
        float outv = dv*rsqrtf(var+1e-5f)*gg[t] + bt[t];
        if (pass == 0)
            g_k2p[(size_t)row*64 + t] = __float2half_rn(outv);
        else
            g_v2t[((size_t)bh*64 + t)*64 + s] = __float2half_rn(outv);
    }
}

// ---------------------------------------------------------------------------
extern "C" void kernel_launch(void* const* d_in, const int* in_sizes, int n_in,
                              void* d_out, int out_size){
    const float* reg_x   = (const float*)d_in[0];
    const int*   tok     = (const int*)d_in[1];
    const int*   rel_idx = (const int*)d_in[2];
    const float* emb_sum  = (const float*)d_in[5];
    const float* rel_emb0 = (const float*)d_in[6];
    const float* Wq  = (const float*)d_in[7];  const float* bq  = (const float*)d_in[8];
    const float* Wk  = (const float*)d_in[9];  const float* bk  = (const float*)d_in[10];
    const float* Wv  = (const float*)d_in[11]; const float* bv  = (const float*)d_in[12];
    const float* Wr0 = (const float*)d_in[13]; const float* br0 = (const float*)d_in[14];
    const float* Wk2 = (const float*)d_in[15]; const float* bk2 = (const float*)d_in[16];
    const float* Wv2 = (const float*)d_in[17]; const float* bv2 = (const float*)d_in[18];
    const float* Wo  = (const float*)d_in[19]; const float* bo  = (const float*)d_in[20];
    const float* lnkg  = (const float*)d_in[21]; const float* lnkb  = (const float*)d_in[22];
    const float* lnvg  = (const float*)d_in[23]; const float* lnvb  = (const float*)d_in[24];
    const float* lnk2g = (const float*)d_in[25]; const float* lnk2b = (const float*)d_in[26];
    const float* lnv2g = (const float*)d_in[27]; const float* lnv2b = (const float*)d_in[28];
    float* out = (float*)d_out;

    cudaFuncSetAttribute(attn_sum_kernel,  cudaFuncAttributeMaxDynamicSharedMemorySize, SUM_SMEM_BYTES);
    cudaFuncSetAttribute(attn_main_kernel, cudaFuncAttributeMaxDynamicSharedMemorySize, MAIN_SMEM_BYTES);
    cudaFuncSetAttribute(gemm_fused, cudaFuncAttributeMaxDynamicSharedMemorySize, GEMM_SMEM_BYTES);

    __half *xp, *attnp, *wqp, *wkp, *wvp, *wop;
    cudaGetSymbolAddress((void**)&xp, g_xp);
    cudaGetSymbolAddress((void**)&attnp, g_attnp);
    cudaGetSymbolAddress((void**)&wqp, g_Wqp);
    cudaGetSymbolAddress((void**)&wkp, g_Wkp);
    cudaGetSymbolAddress((void**)&wvp, g_Wvp);
    cudaGetSymbolAddress((void**)&wop, g_Wop);

    dim3 wgrid(32,32,4);
    dim3 wblk(32,8);
    dim3 ggrid(E_/128, MROWS/128);   // (8, 32)

    cvtA_kernel<<<MROWS*E_/4/256, 256>>>(reg_x, xp);                    // 1
    cvtW_kernel<<<wgrid, wblk>>>(Wq, Wk, Wv, Wo);                       // 2 (all 4 weights)
    gemm_fused<<<ggrid, 256, GEMM_SMEM_BYTES>>>(xp, wkp, bk, (float*)0, 1, lnkg, lnkb); // 3
    gemm_fused<<<ggrid, 256, GEMM_SMEM_BYTES>>>(xp, wvp, bv, (float*)0, 2, lnvg, lnvb); // 4 (profiled)
    gemm_fused<<<ggrid, 256, GEMM_SMEM_BYTES>>>(xp, wqp, bq, (float*)0, 0, (const float*)0, (const float*)0); // 5
    r0_kernel<<<Z_*H_, 64>>>(rel_emb0, Wr0, br0);                       // 6
    idx8_kernel<<<(B_*TOTLEN*R_/4 + 255)/256, 256>>>(rel_idx);          // 7

    attn_sum_kernel<<<dim3(B_*H_, SPLITS), 128, SUM_SMEM_BYTES>>>(tok, emb_sum);
    combine_kernel<<<B_*H_*S_, 64>>>();
    k2v2_kernel<<<B_*H_*S_, 64>>>(Wk2, bk2, Wv2, bv2, lnk2g, lnk2b, lnv2g, lnv2b);

    attn_main_kernel<<<dim3(R_/128, H_, B_), 128, MAIN_SMEM_BYTES>>>();

    gemm_fused<<<ggrid, 256, GEMM_SMEM_BYTES>>>(attnp, wop, bo, out, 3, (const float*)0, (const float*)0);
}

// round 17
// speedup vs baseline: 1.6284x; 1.0136x over previous
#include <cuda_runtime.h>
#include <cuda_fp16.h>
#include <math.h>

#define H_ 16
#define D_ 64
#define R_ 2048
#define S_ 64
#define B_ 2
#define E_ 1024
#define Z_ 64
#define SCALE_ 0.125f
#define MROWS (R_*B_)   /* 4096 */
#define SPLITS 8
#define TOTLEN (S_+R_)  /* 2112 */

// ---------------- scratch (device globals: allocation-free) ----------------
__device__ __half g_xp[MROWS*E_];
__device__ __half g_attnp[MROWS*E_];
__device__ __half g_Wqp[E_*E_];
__device__ __half g_Wkp[E_*E_];
__device__ __half g_Wvp[E_*E_];
__device__ __half g_Wop[E_*E_];
__device__ __half g_qp[B_*H_*R_*D_];
__device__ __half g_kp[B_*H_*R_*D_];
__device__ __half g_vt[B_*H_*D_*R_];
__device__ __half g_r0p[H_*Z_*D_];
__device__ __half g_k2p[B_*H_*S_*D_];
__device__ __half g_v2t[B_*H_*D_*S_];
__device__ unsigned char g_idx8[B_*TOTLEN*R_];
__device__ float g_pacc[B_*H_*SPLITS*S_*D_];
__device__ float g_pm[B_*H_*SPLITS*S_];
__device__ float g_pl[B_*H_*SPLITS*S_];

// ---------------- helpers ---------------------------------------------------
__device__ __forceinline__ unsigned packh2(float lo, float hi){
    unsigned u;
    asm("{.reg .f16 l,h;\n cvt.rn.f16.f32 l,%1;\n cvt.rn.f16.f32 h,%2;\n mov.b32 %0,{l,h};}\n"
        : "=r"(u) : "f"(lo), "f"(hi));
    return u;
}
__device__ __forceinline__ unsigned sm2u(const void* p){
    return (unsigned)__cvta_generic_to_shared(p);
}
__device__ __forceinline__ void ldsm4(unsigned* r, unsigned addr){
    asm volatile("ldmatrix.sync.aligned.m8n8.x4.shared.b16 {%0,%1,%2,%3},[%4];"
        : "=r"(r[0]), "=r"(r[1]), "=r"(r[2]), "=r"(r[3]) : "r"(addr));
}
__device__ __forceinline__ void mma_f16(float* c, const unsigned* a,
        unsigned b0, unsigned b1){
    asm volatile(
        "mma.sync.aligned.m16n8k16.row.col.f32.f16.f16.f32 "
        "{%0,%1,%2,%3},{%4,%5,%6,%7},{%8,%9},{%0,%1,%2,%3};"
        : "+f"(c[0]), "+f"(c[1]), "+f"(c[2]), "+f"(c[3])
        : "r"(a[0]), "r"(a[1]), "r"(a[2]), "r"(a[3]), "r"(b0), "r"(b1));
}
__device__ __forceinline__ void cp16(void* dst, const void* src){
    unsigned d = (unsigned)__cvta_generic_to_shared(dst);
    asm volatile("cp.async.cg.shared.global [%0],[%1],16;" :: "r"(d), "l"(src));
}
#define CP_COMMIT() asm volatile("cp.async.commit_group;" ::: "memory")
#define CP_WAIT0()  asm volatile("cp.async.wait_group 0;" ::: "memory")
#define CP_WAIT1()  asm volatile("cp.async.wait_group 1;" ::: "memory")

#define LDSM_OFFS()                                                          \
    int arow = (lane&7) + ((lane>>3)&1)*8;                                   \
    int akh  = ((lane>>4)&1)*8;                                              \
    int brow = (lane&7) + ((lane>>4)&1)*8;                                   \
    int bkh  = ((lane>>3)&1)*8;

// -------- pre-conversion kernels -------------------------------------------
__global__ __launch_bounds__(256) void cvtA_kernel(const float* __restrict__ src,
        __half* __restrict__ dst){
    size_t i = (size_t)blockIdx.x*256 + threadIdx.x;
    size_t m = i >> 8; int kq = (int)(i & 255) * 4;
    float4 v = *(const float4*)(src + m*E_ + kq);
    uint2 u; u.x = packh2(v.x, v.y); u.y = packh2(v.z, v.w);
    *(uint2*)&dst[m*E_ + kq] = u;
}
// all four weights in one launch: blockIdx.z selects (W, out)
__global__ void cvtW_kernel(const float* __restrict__ W0, const float* __restrict__ W1,
        const float* __restrict__ W2, const float* __restrict__ W3){
    __shared__ float tile[32][33];
    const float* W; __half* out;
    switch (blockIdx.z){
        case 0: W = W0; out = g_Wqp; break;
        case 1: W = W1; out = g_Wkp; break;
        case 2: W = W2; out = g_Wvp; break;
        default: W = W3; out = g_Wop; break;
    }
    int k0 = blockIdx.y*32, n0 = blockIdx.x*32;
    int tx = threadIdx.x, ty = threadIdx.y;  // 32 x 8
    #pragma unroll
    for (int j=0;j<4;j++)
        tile[ty+8*j][tx] = W[(size_t)(k0+ty+8*j)*E_ + n0 + tx];
    __syncthreads();
    #pragma unroll
    for (int j=0;j<4;j++){
        int n = n0 + ty + 8*j;
        out[(size_t)n*E_ + k0 + tx] = __float2half_rn(tile[tx][ty+8*j]);
    }
}

// ---------------- fp16 GEMM + fused epilogue (3-stage pipeline, R11) --------
#define GSTG 10240
#define GEMM_SMEM_BYTES (3*GSTG*2)   /* 61440 */

__device__ __forceinline__ void g_stage_h(__half* smh, int s,
        const __half* Ag, const __half* Wg, int t){
    __half* base = smh + s*GSTG;
    #pragma unroll
    for (int j=0;j<2;j++){
        int c = t + 256*j; int row = c>>2, seg = c&3;   // 128 rows x 4 segs (BK=32)
        cp16(base + row*40 + seg*8, Ag + (size_t)row*E_ + seg*8);
        cp16(base + 5120 + row*40 + seg*8, Wg + (size_t)row*E_ + seg*8);
    }
}

__global__ __launch_bounds__(256) void gemm_fused(const __half* __restrict__ A,
        const __half* __restrict__ W, const float* __restrict__ bias,
        float* __restrict__ outF, int mode,
        const float* __restrict__ gg, const float* __restrict__ bb){
    extern __shared__ __half smh[];
    int t = threadIdx.x, lane = t & 31, w = t >> 5;
    int wm = w >> 1, wn = w & 1;
    int tq = lane >> 2, te = lane & 3;
    LDSM_OFFS();
    int row0 = blockIdx.y * 128, n0 = blockIdx.x * 128;
    const __half* Abase = A + (size_t)row0*E_;
    const __half* Wbase = W + (size_t)n0*E_;

    float acc[2][8][4];
    #pragma unroll
    for (int m=0;m<2;m++)
        #pragma unroll
        for (int n=0;n<8;n++)
            #pragma unroll
            for (int j=0;j<4;j++) acc[m][n][j]=0.f;

    g_stage_h(smh, 0, Abase, Wbase, t); CP_COMMIT();
    g_stage_h(smh, 1, Abase + 32, Wbase + 32, t); CP_COMMIT();

    for (int it=0; it<32; it++){
        if (it < 31){ CP_WAIT1(); } else { CP_WAIT0(); }
        __syncthreads();
        if (it + 2 < 32){
            g_stage_h(smh, (it+2)%3, Abase + (it+2)*32, Wbase + (it+2)*32, t);
            CP_COMMIT();
        }
        __half* As = smh + (it%3)*GSTG;
        __half* Bs = As + 5120;
        #pragma unroll
        for (int ks2=0; ks2<2; ks2++){
            int k0 = ks2*16;
            unsigned a[2][4];
            ldsm4(a[0], sm2u(As + (wm*32 +      arow)*40 + k0 + akh));
            ldsm4(a[1], sm2u(As + (wm*32 + 16 + arow)*40 + k0 + akh));
            #pragma unroll
            for (int p=0; p<4; p++){
                unsigned bbf[4];
                ldsm4(bbf, sm2u(Bs + (wn*64 + p*16 + brow)*40 + k0 + bkh));
                mma_f16(acc[0][2*p],   a[0], bbf[0], bbf[1]);
                mma_f16(acc[0][2*p+1], a[0], bbf[2], bbf[3]);
                mma_f16(acc[1][2*p],   a[1], bbf[0], bbf[1]);
                mma_f16(acc[1][2*p+1], a[1], bbf[2], bbf[3]);
            }
        }
        __syncthreads();
    }

    int h = blockIdx.x*2 + wn;
    #pragma unroll
    for (int mf=0; mf<2; mf++){
        #pragma unroll
        for (int rsel=0; rsel<2; rsel++){
            int m = row0 + wm*32 + mf*16 + tq + rsel*8;
            float v[16];
            #pragma unroll
            for (int nf=0; nf<8; nf++){
                int c = nf*8 + 2*te;
                v[2*nf]   = acc[mf][nf][2*rsel]   + __ldg(&bias[h*64 + c]);
                v[2*nf+1] = acc[mf][nf][2*rsel+1] + __ldg(&bias[h*64 + c + 1]);
            }
            if (mode == 3){
                #pragma unroll
                for (int nf=0; nf<8; nf++)
                    *(float2*)&outF[(size_t)m*E_ + h*64 + nf*8 + 2*te] =
                        make_float2(v[2*nf], v[2*nf+1]);
            } else if (mode == 0){
                int r = m>>1, b = m&1, bh = b*H_ + h;
                __half* dst = g_qp + ((size_t)bh*R_ + r)*64;
                #pragma unroll
                for (int nf=0; nf<8; nf++){
                    int c = nf*8 + 2*te;
                    *(unsigned*)&dst[c] = packh2(v[2*nf]*SCALE_, v[2*nf+1]*SCALE_);
                }
            } else {
                int r = m>>1, b = m&1, bh = b*H_ + h;
                float s = 0.f;
                #pragma unroll
                for (int i=0;i<16;i++) s += v[i];
                s += __shfl_xor_sync(0xffffffffu, s, 1);
                s += __shfl_xor_sync(0xffffffffu, s, 2);
                float mean = s*(1.f/64.f);
                float var = 0.f;
                #pragma unroll
                for (int i=0;i<16;i++){ float d = v[i]-mean; var += d*d; }
                var += __shfl_xor_sync(0xffffffffu, var, 1);
                var += __shfl_xor_sync(0xffffffffu, var, 2);
                float scl = rsqrtf(var*(1.f/64.f) + 1e-5f);
                if (mode == 1){
                    __half* dst = g_kp + ((size_t)bh*R_ + r)*64;
                    #pragma unroll
                    for (int nf=0; nf<8; nf++){
                        int c = nf*8 + 2*te;
                        *(unsigned*)&dst[c] = packh2(
                            (v[2*nf]-mean)*scl*__ldg(&gg[c]) + __ldg(&bb[c]),
                            (v[2*nf+1]-mean)*scl*__ldg(&gg[c+1]) + __ldg(&bb[c+1]));
                    }
                } else {
                    #pragma unroll
                    for (int nf=0; nf<8; nf++){
                        int c = nf*8 + 2*te;
                        g_vt[((size_t)bh*64 + c)*R_ + r] = __float2half_rn(
                            (v[2*nf]-mean)*scl*__ldg(&gg[c]) + __ldg(&bb[c]));
                        g_vt[((size_t)bh*64 + c+1)*R_ + r] = __float2half_rn(
                            (v[2*nf+1]-mean)*scl*__ldg(&gg[c+1]) + __ldg(&bb[c+1]));
                    }
                }
            }
        }
    }
}

// -------- r0p[h][z][d] = fp16( rel_emb0@Wr0 + br0 ) -------------------------
__global__ __launch_bounds__(64) void r0_kernel(const float* __restrict__ rel_emb0,
        const float* __restrict__ Wr0, const float* __restrict__ br0){
    int z = blockIdx.x >> 4, h = blockIdx.x & 15;
    int d = threadIdx.x;
    float a = br0[h*64+d];
    #pragma unroll 8
    for (int c=0;c<64;c++) a += rel_emb0[z*64+c]*Wr0[c*E_ + h*64 + d];
    g_r0p[(h*Z_ + z)*64 + d] = __float2half_rn(a);
}

// -------- compress rel_idx (int32 < 64) to u8 -------------------------------
__global__ __launch_bounds__(256) void idx8_kernel(const int* __restrict__ rel){
    size_t i = (size_t)blockIdx.x*256 + threadIdx.x;
    int4 v = ((const int4*)rel)[i];
    uchar4 u; u.x=(unsigned char)v.x; u.y=(unsigned char)v.y;
    u.z=(unsigned char)v.z; u.w=(unsigned char)v.w;
    ((uchar4*)g_idx8)[i] = u;
}

// ================= fp16 main attention: 128q/CTA, 4 warps (R11) =============
#define HKB(b) ((b)*4608)
#define HVB(b) (9216 + (b)*4608)
#define MQRF   9216
#define MAIN_SMEM_BYTES (36864 + 128*65*4)   /* 70144 */

__device__ __forceinline__ void stage_kv_h(__half* smh, int kbo, int vbo,
        const __half* kg, const __half* vg, size_t vstride, int t){
    #pragma unroll
    for (int j=0;j<4;j++){
        int c = t + 128*j; int row = c>>3, seg = c&7;
        cp16(smh + kbo + row*72 + seg*8, kg + (size_t)row*64 + seg*8);
        cp16(smh + vbo + row*72 + seg*8, vg + (size_t)row*vstride + seg*8);
    }
}

__global__ __launch_bounds__(128,2) void attn_main_kernel(){
    extern __shared__ char smraw[];
    __half* smh = (__half*)smraw;
    float* smf = (float*)smraw;
    int t = threadIdx.x, lane = t & 31, w = t >> 5;
    int tq = lane >> 2, te = lane & 3;
    LDSM_OFFS();
    int b = blockIdx.z, h = blockIdx.y, bh = b*H_ + h;
    int q0 = blockIdx.x * 128;
    int r0w = w*32 + tq;

    {   // Q: 128 rows x 64 halves = 1024 cp16; r0: 64x64 = 512 cp16
        const __half* qg = g_qp + ((size_t)bh*R_ + q0)*64;
        const __half* rg = g_r0p + (size_t)h*Z_*64;
        #pragma unroll
        for (int j=0;j<8;j++){
            int c = t + 128*j; int row = c>>3, seg = c&7;
            cp16(smh + row*72 + seg*8, qg + (size_t)row*64 + seg*8);
        }
        #pragma unroll
        for (int j=0;j<4;j++){
            int c = t + 128*j; int row = c>>3, seg = c&7;
            cp16(smh + HVB(0) + row*72 + seg*8, rg + (size_t)row*64 + seg*8);
        }
    }
    CP_COMMIT(); CP_WAIT0(); __syncthreads();

    unsigned qa[2][4][4];
    #pragma unroll
    for (int mf=0; mf<2; mf++)
        #pragma unroll
        for (int j2=0; j2<4; j2++)
            ldsm4(qa[mf][j2], sm2u(smh + (w*32 + mf*16 + arow)*72 + j2*16 + akh));

    float S[2][8][4];
    #pragma unroll
    for (int mf=0;mf<2;mf++)
        #pragma unroll
        for (int nf=0;nf<8;nf++){ S[mf][nf][0]=S[mf][nf][1]=S[mf][nf][2]=S[mf][nf][3]=0.f; }

    // QR = Q x r0^T
    #pragma unroll
    for (int j2=0; j2<4; j2++)
        #pragma unroll
        for (int p=0; p<4; p++){
            unsigned bbf[4];
            ldsm4(bbf, sm2u(smh + HVB(0) + (p*16 + brow)*72 + j2*16 + bkh));
            mma_f16(S[0][2*p],   qa[0][j2], bbf[0], bbf[1]);
            mma_f16(S[0][2*p+1], qa[0][j2], bbf[2], bbf[3]);
            mma_f16(S[1][2*p],   qa[1][j2], bbf[0], bbf[1]);
            mma_f16(S[1][2*p+1], qa[1][j2], bbf[2], bbf[3]);
        }
    #pragma unroll
    for (int mf=0; mf<2; mf++)
        #pragma unroll
        for (int nf=0; nf<8; nf++){
            int row = r0w + mf*16, c = nf*8 + 2*te;
            smf[MQRF + row*65 + c]       = S[mf][nf][0];
            smf[MQRF + row*65 + c+1]     = S[mf][nf][1];
            smf[MQRF + (row+8)*65 + c]   = S[mf][nf][2];
            smf[MQRF + (row+8)*65 + c+1] = S[mf][nf][3];
        }
    __syncthreads();

    stage_kv_h(smh, HKB(0), HVB(0),
               g_k2p + (size_t)bh*S_*64, g_v2t + (size_t)bh*64*S_, 64, t);
    CP_COMMIT();

    float O[2][8][4];
    #pragma unroll
    for (int mf=0;mf<2;mf++)
        #pragma unroll
        for (int nf=0;nf<8;nf++){ O[mf][nf][0]=O[mf][nf][1]=O[mf][nf][2]=O[mf][nf][3]=0.f; }
    float mr[2][2], lr[2][2];
    #pragma unroll
    for (int mf=0;mf<2;mf++){ mr[mf][0]=mr[mf][1]=-1e30f; lr[mf][0]=lr[mf][1]=0.f; }

    const unsigned char* igbase = g_idx8 + ((size_t)b*TOTLEN + S_ + q0)*R_;

    for (int kt = 0; kt < 33; kt++){
        if (kt < 32){
            int k0n = kt*64;
            int nb = (kt+1)&1;
            stage_kv_h(smh, HKB(nb), HVB(nb),
                       g_kp + ((size_t)bh*R_ + k0n)*64,
                       g_vt + (size_t)bh*64*R_ + k0n, R_, t);
            CP_COMMIT(); CP_WAIT1();
        } else {
            CP_WAIT0();
        }
        __syncthreads();
        int bu = kt&1;

        unsigned ix0[2][8], ix1[2][8];
        if (kt >= 1){
            const unsigned char* ig = igbase + (kt-1)*64;
            #pragma unroll
            for (int mf=0; mf<2; mf++)
                #pragma unroll
                for (int nf=0; nf<8; nf++){
                    int row = r0w + mf*16;
                    ix0[mf][nf] = *(const unsigned short*)(ig + (size_t)row*R_ + nf*8 + 2*te);
                    ix1[mf][nf] = *(const unsigned short*)(ig + (size_t)(row+8)*R_ + nf*8 + 2*te);
                }
        }

        #pragma unroll
        for (int mf=0;mf<2;mf++)
            #pragma unroll
            for (int nf=0;nf<8;nf++){ S[mf][nf][0]=S[mf][nf][1]=S[mf][nf][2]=S[mf][nf][3]=0.f; }
        #pragma unroll
        for (int j2=0; j2<4; j2++)
            #pragma unroll
            for (int p=0; p<4; p++){
                unsigned bbf[4];
                ldsm4(bbf, sm2u(smh + HKB(bu) + (p*16 + brow)*72 + j2*16 + bkh));
                mma_f16(S[0][2*p],   qa[0][j2], bbf[0], bbf[1]);
                mma_f16(S[0][2*p+1], qa[0][j2], bbf[2], bbf[3]);
                mma_f16(S[1][2*p],   qa[1][j2], bbf[0], bbf[1]);
                mma_f16(S[1][2*p+1], qa[1][j2], bbf[2], bbf[3]);
            }

        if (kt >= 1){
            #pragma unroll
            for (int mf=0; mf<2; mf++)
                #pragma unroll
                for (int nf=0; nf<8; nf++){
                    int row = r0w + mf*16;
                    S[mf][nf][0] += smf[MQRF + row*65 + (ix0[mf][nf]&255)];
                    S[mf][nf][1] += smf[MQRF + row*65 + (ix0[mf][nf]>>8)];
                    S[mf][nf][2] += smf[MQRF + (row+8)*65 + (ix1[mf][nf]&255)];
                    S[mf][nf][3] += smf[MQRF + (row+8)*65 + (ix1[mf][nf]>>8)];
                }
        }

        #pragma unroll
        for (int mf=0; mf<2; mf++){
            float tm0 = -1e30f, tm1 = -1e30f;
            #pragma unroll
            for (int nf=0; nf<8; nf++){
                tm0 = fmaxf(tm0, fmaxf(S[mf][nf][0], S[mf][nf][1]));
                tm1 = fmaxf(tm1, fmaxf(S[mf][nf][2], S[mf][nf][3]));
            }
            tm0 = fmaxf(tm0, __shfl_xor_sync(0xffffffffu, tm0, 1));
            tm0 = fmaxf(tm0, __shfl_xor_sync(0xffffffffu, tm0, 2));
            tm1 = fmaxf(tm1, __shfl_xor_sync(0xffffffffu, tm1, 1));
            tm1 = fmaxf(tm1, __shfl_xor_sync(0xffffffffu, tm1, 2));
            float mn0 = fmaxf(mr[mf][0], tm0), mn1 = fmaxf(mr[mf][1], tm1);
            float f0 = __expf(mr[mf][0] - mn0), f1 = __expf(mr[mf][1] - mn1);
            mr[mf][0] = mn0; mr[mf][1] = mn1;
            float rs0 = 0.f, rs1 = 0.f;
            #pragma unroll
            for (int nf=0; nf<8; nf++){
                S[mf][nf][0] = __expf(S[mf][nf][0]-mn0); rs0 += S[mf][nf][0];
                S[mf][nf][1] = __expf(S[mf][nf][1]-mn0); rs0 += S[mf][nf][1];
                S[mf][nf][2] = __expf(S[mf][nf][2]-mn1); rs1 += S[mf][nf][2];
                S[mf][nf][3] = __expf(S[mf][nf][3]-mn1); rs1 += S[mf][nf][3];
            }
            rs0 += __shfl_xor_sync(0xffffffffu, rs0, 1);
            rs0 += __shfl_xor_sync(0xffffffffu, rs0, 2);
            rs1 += __shfl_xor_sync(0xffffffffu, rs1, 1);
            rs1 += __shfl_xor_sync(0xffffffffu, rs1, 2);
            lr[mf][0] = lr[mf][0]*f0 + rs0;
            lr[mf][1] = lr[mf][1]*f1 + rs1;
            #pragma unroll
            for (int nf=0; nf<8; nf++){
                O[mf][nf][0]*=f0; O[mf][nf][1]*=f0;
                O[mf][nf][2]*=f1; O[mf][nf][3]*=f1;
            }
        }

        #pragma unroll
        for (int j2=0; j2<4; j2++){
            unsigned pa[2][4];
            #pragma unroll
            for (int mf=0; mf<2; mf++){
                pa[mf][0] = packh2(S[mf][2*j2][0],   S[mf][2*j2][1]);
                pa[mf][1] = packh2(S[mf][2*j2][2],   S[mf][2*j2][3]);
                pa[mf][2] = packh2(S[mf][2*j2+1][0], S[mf][2*j2+1][1]);
                pa[mf][3] = packh2(S[mf][2*j2+1][2], S[mf][2*j2+1][3]);
            }
            #pragma unroll
            for (int pd=0; pd<4; pd++){
                unsigned bv[4];
                ldsm4(bv, sm2u(smh + HVB(bu) + (pd*16 + brow)*72 + j2*16 + bkh));
                mma_f16(O[0][2*pd],   pa[0], bv[0], bv[1]);
                mma_f16(O[0][2*pd+1], pa[0], bv[2], bv[3]);
                mma_f16(O[1][2*pd],   pa[1], bv[0], bv[1]);
                mma_f16(O[1][2*pd+1], pa[1], bv[2], bv[3]);
            }
        }
        __syncthreads();
    }

    #pragma unroll
    for (int mf=0; mf<2; mf++){
        float inv0 = 1.f/lr[mf][0], inv1 = 1.f/lr[mf][1];
        int qg0 = q0 + r0w + mf*16;
        __half* dst0 = g_attnp + ((size_t)(qg0*B_ + b))*E_ + h*64;
        __half* dst1 = g_attnp + ((size_t)((qg0+8)*B_ + b))*E_ + h*64;
        #pragma unroll
        for (int nf=0; nf<8; nf++){
            int c = nf*8 + 2*te;
            *(unsigned*)&dst0[c] = packh2(O[mf][nf][0]*inv0, O[mf][nf][1]*inv0);
            *(unsigned*)&dst1[c] = packh2(O[mf][nf][2]*inv1, O[mf][nf][3]*inv1);
        }
    }
}

// ================= fp16 sum attention (split-K, 64q, R11) ===================
#define SKB(b) ((b)*4608)
#define SVB(b) (9216 + (b)*4608)
#define AQRF   9216
#define SUM_SMEM_BYTES (36864 + 64*68*4)   /* 54272 */

__global__ __launch_bounds__(128,2) void attn_sum_kernel(const int* __restrict__ tok,
        const float* __restrict__ emb_sum){
    extern __shared__ char smraw[];
    __half* smh = (__half*)smraw;
    float* smf = (float*)smraw;
    int t = threadIdx.x, lane = t & 31, w = t >> 5;
    int tq = lane >> 2, te = lane & 3;
    LDSM_OFFS();
    int bh = blockIdx.x, split = blockIdx.y;
    int b = bh >> 4, h = bh & 15;

    {
        int row = t>>1, halfc = (t&1)*32;
        int token = tok[b*S_ + row];
        const float4* p = (const float4*)(emb_sum + (size_t)token*E_ + h*64 + halfc);
        #pragma unroll
        for (int j=0;j<8;j++){
            float4 v = p[j]; int c = halfc + j*4;
            uint2 u; u.x = packh2(v.x*SCALE_, v.y*SCALE_);
            u.y = packh2(v.z*SCALE_, v.w*SCALE_);
            *(uint2*)&smh[row*72 + c] = u;
        }
        const __half* rg = g_r0p + (size_t)h*Z_*64;
        #pragma unroll
        for (int j=0;j<4;j++){
            int c = t + 128*j; int rr = c>>3, seg = c&7;
            cp16(smh + SVB(0) + rr*72 + seg*8, rg + (size_t)rr*64 + seg*8);
        }
    }
    CP_COMMIT(); CP_WAIT0(); __syncthreads();

    unsigned qa[4][4];
    #pragma unroll
    for (int j2=0; j2<4; j2++)
        ldsm4(qa[j2], sm2u(smh + (w*16 + arow)*72 + j2*16 + akh));

    float S[8][4];
    #pragma unroll
    for (int nf=0;nf<8;nf++){ S[nf][0]=S[nf][1]=S[nf][2]=S[nf][3]=0.f; }
    #pragma unroll
    for (int j2=0; j2<4; j2++)
        #pragma unroll
        for (int p=0; p<4; p++){
            unsigned bbf[4];
            ldsm4(bbf, sm2u(smh + SVB(0) + (p*16 + brow)*72 + j2*16 + bkh));
            mma_f16(S[2*p],   qa[j2], bbf[0], bbf[1]);
            mma_f16(S[2*p+1], qa[j2], bbf[2], bbf[3]);
        }
    #pragma unroll
    for (int nf=0; nf<8; nf++){
        int row = w*16 + tq, c = nf*8 + 2*te;
        smf[AQRF + row*68 + c]       = S[nf][0];
        smf[AQRF + row*68 + c+1]     = S[nf][1];
        smf[AQRF + (row+8)*68 + c]   = S[nf][2];
        smf[AQRF + (row+8)*68 + c+1] = S[nf][3];
    }
    __syncthreads();

    int kbase = split*256;
    {
        const __half* kg = g_kp + ((size_t)bh*R_ + kbase)*64;
        const __half* vg = g_vt + (size_t)bh*64*R_ + kbase;
        #pragma unroll
        for (int j=0;j<4;j++){
            int c = t + 128*j; int row = c>>3, seg = c&7;
            cp16(smh + SKB(0) + row*72 + seg*8, kg + (size_t)row*64 + seg*8);
            cp16(smh + SVB(0) + row*72 + seg*8, vg + (size_t)row*R_ + seg*8);
        }
    }
    CP_COMMIT();

    float O[8][4];
    #pragma unroll
    for (int nf=0;nf<8;nf++){ O[nf][0]=O[nf][1]=O[nf][2]=O[nf][3]=0.f; }
    float mr0 = -1e30f, mr1 = -1e30f, lr0 = 0.f, lr1 = 0.f;
    const unsigned char* igbase = g_idx8 + (size_t)b*TOTLEN*R_;

    for (int kt = 0; kt < 4; kt++){
        if (kt < 3){
            int k0n = kbase + (kt+1)*64;
            int nb = (kt+1)&1;
            const __half* kg = g_kp + ((size_t)bh*R_ + k0n)*64;
            const __half* vg = g_vt + (size_t)bh*64*R_ + k0n;
            #pragma unroll
            for (int j=0;j<4;j++){
                int c = t + 128*j; int row = c>>3, seg = c&7;
                cp16(smh + SKB(nb) + row*72 + seg*8, kg + (size_t)row*64 + seg*8);
                cp16(smh + SVB(nb) + row*72 + seg*8, vg + (size_t)row*R_ + seg*8);
            }
            CP_COMMIT(); CP_WAIT1();
        } else {
            CP_WAIT0();
        }
        __syncthreads();
        int bu = kt&1;

        unsigned ix0[8], ix1[8];
        {
            const unsigned char* ig = igbase + kbase + kt*64;
            #pragma unroll
            for (int nf=0; nf<8; nf++){
                int row = w*16 + tq;
                ix0[nf] = *(const unsigned short*)(ig + (size_t)row*R_ + nf*8 + 2*te);
                ix1[nf] = *(const unsigned short*)(ig + (size_t)(row+8)*R_ + nf*8 + 2*te);
            }
        }

        #pragma unroll
        for (int nf=0;nf<8;nf++){ S[nf][0]=S[nf][1]=S[nf][2]=S[nf][3]=0.f; }
        #pragma unroll
        for (int j2=0; j2<4; j2++)
            #pragma unroll
            for (int p=0; p<4; p++){
                unsigned bbf[4];
                ldsm4(bbf, sm2u(smh + SKB(bu) + (p*16 + brow)*72 + j2*16 + bkh));
                mma_f16(S[2*p],   qa[j2], bbf[0], bbf[1]);
                mma_f16(S[2*p+1], qa[j2], bbf[2], bbf[3]);
            }

        {
            int row = w*16 + tq;
            #pragma unroll
            for (int nf=0; nf<8; nf++){
                S[nf][0] += smf[AQRF + row*68 + (ix0[nf]&255)];
                S[nf][1] += smf[AQRF + row*68 + (ix0[nf]>>8)];
                S[nf][2] += smf[AQRF + (row+8)*68 + (ix1[nf]&255)];
                S[nf][3] += smf[AQRF + (row+8)*68 + (ix1[nf]>>8)];
            }
        }

        float tm0 = -1e30f, tm1 = -1e30f;
        #pragma unroll
        for (int nf=0; nf<8; nf++){
            tm0 = fmaxf(tm0, fmaxf(S[nf][0], S[nf][1]));
            tm1 = fmaxf(tm1, fmaxf(S[nf][2], S[nf][3]));
        }
        tm0 = fmaxf(tm0, __shfl_xor_sync(0xffffffffu, tm0, 1));
        tm0 = fmaxf(tm0, __shfl_xor_sync(0xffffffffu, tm0, 2));
        tm1 = fmaxf(tm1, __shfl_xor_sync(0xffffffffu, tm1, 1));
        tm1 = fmaxf(tm1, __shfl_xor_sync(0xffffffffu, tm1, 2));
        float mn0 = fmaxf(mr0, tm0), mn1 = fmaxf(mr1, tm1);
        float f0 = __expf(mr0 - mn0), f1 = __expf(mr1 - mn1);
        mr0 = mn0; mr1 = mn1;
        float rs0 = 0.f, rs1 = 0.f;
        #pragma unroll
        for (int nf=0; nf<8; nf++){
            S[nf][0] = __expf(S[nf][0]-mn0); rs0 += S[nf][0];
            S[nf][1] = __expf(S[nf][1]-mn0); rs0 += S[nf][1];
            S[nf][2] = __expf(S[nf][2]-mn1); rs1 += S[nf][2];
            S[nf][3] = __expf(S[nf][3]-mn1); rs1 += S[nf][3];
        }
        rs0 += __shfl_xor_sync(0xffffffffu, rs0, 1);
        rs0 += __shfl_xor_sync(0xffffffffu, rs0, 2);
        rs1 += __shfl_xor_sync(0xffffffffu, rs1, 1);
        rs1 += __shfl_xor_sync(0xffffffffu, rs1, 2);
        lr0 = lr0*f0 + rs0; lr1 = lr1*f1 + rs1;
        #pragma unroll
        for (int nf=0; nf<8; nf++){
            O[nf][0]*=f0; O[nf][1]*=f0; O[nf][2]*=f1; O[nf][3]*=f1;
        }
        #pragma unroll
        for (int j2=0; j2<4; j2++){
            unsigned pa[4];
            pa[0] = packh2(S[2*j2][0],   S[2*j2][1]);
            pa[1] = packh2(S[2*j2][2],   S[2*j2][3]);
            pa[2] = packh2(S[2*j2+1][0], S[2*j2+1][1]);
            pa[3] = packh2(S[2*j2+1][2], S[2*j2+1][3]);
            #pragma unroll
            for (int pd=0; pd<4; pd++){
                unsigned bv[4];
                ldsm4(bv, sm2u(smh + SVB(bu) + (pd*16 + brow)*72 + j2*16 + bkh));
                mma_f16(O[2*pd],   pa, bv[0], bv[1]);
                mma_f16(O[2*pd+1], pa, bv[2], bv[3]);
            }
        }
        __syncthreads();
    }

    int pb = bh*SPLITS + split;
    int s0 = w*16 + tq;
    #pragma unroll
    for (int nf=0; nf<8; nf++){
        int c = nf*8 + 2*te;
        *(float2*)&g_pacc[((size_t)pb*S_ + s0)*64 + c] =
            make_float2(O[nf][0], O[nf][1]);
        *(float2*)&g_pacc[((size_t)pb*S_ + s0 + 8)*64 + c] =
            make_float2(O[nf][2], O[nf][3]);
    }
    if (te == 0){
        g_pm[pb*S_ + s0] = mr0;    g_pm[pb*S_ + s0 + 8] = mr1;
        g_pl[pb*S_ + s0] = lr0;    g_pl[pb*S_ + s0 + 8] = lr1;
    }
}

// ---- fused: combine split-K partials + k2/v2 projections + LN -> fp16 ------
__global__ __launch_bounds__(64) void combine_k2v2_kernel(
        const float* __restrict__ Wk2, const float* __restrict__ bk2,
        const float* __restrict__ Wv2, const float* __restrict__ bv2,
        const float* __restrict__ g1, const float* __restrict__ b1,
        const float* __restrict__ g2, const float* __restrict__ b2){
    __shared__ float xr[64];
    __shared__ float red[2];
    int row = blockIdx.x, t = threadIdx.x;
    int bh = row >> 6, s = row & 63;

    // --- combine phase: xr[t] = sumx2[row][t] ---
    {
        float mv[SPLITS];
        float M = -1e30f;
        #pragma unroll
        for (int i=0;i<SPLITS;i++){
            mv[i] = g_pm[(bh*SPLITS + i)*S_ + s];
            M = fmaxf(M, mv[i]);
        }
        float L = 0.f, acc = 0.f;
        #pragma unroll
        for (int i=0;i<SPLITS;i++){
            float w = __expf(mv[i] - M);
            acc += w * g_pacc[((size_t)(bh*SPLITS + i)*S_ + s)*64 + t];
            L   += w * g_pl[(bh*SPLITS + i)*S_ + s];
        }
        xr[t] = acc / L;
    }
    __syncthreads();

    // --- projection + LN phase (two passes) ---
    #pragma unroll
    for (int pass=0; pass<2; pass++){
        const float* W  = pass ? Wv2 : Wk2;
        const float* bb = pass ? bv2 : bk2;
        const float* gg = pass ? g2  : g1;
        const float* bt = pass ? b2  : b1;
        float a = bb[t];
        #pragma unroll 8
        for (int j=0;j<64;j++) a += xr[j]*W[j*64+t];
        float sred = a;
        #pragma unroll
        for (int o=16;o;o>>=1) sred += __shfl_xor_sync(0xffffffffu, sred, o);
        if ((t&31)==0) red[t>>5] = sred;
        __syncthreads();
        float mean = (red[0]+red[1]) * (1.f/64.f);
        __syncthreads();
        float dv = a - mean;
        float v2 = dv*dv;
        #pragma unroll
        for (int o=16;o;o>>=1) v2 += __shfl_xor_sync(0xffffffffu, v2, o);
        if ((t&31)==0) red[t>>5] = v2;
        __syncthreads();
        float var = (red[0]+red[1]) * (1.f/64.f);
        __syncthreads();
        float outv = dv*rsqrtf(var+1e-5f)*gg[t] + bt[t];
        if (pass == 0)
            g_k2p[(size_t)row*64 + t] = __float2half_rn(outv);
        else
            g_v2t[((size_t)bh*64 + t)*64 + s] = __float2half_rn(outv);
    }
}

// ---------------------------------------------------------------------------
extern "C" void kernel_launch(void* const* d_in, const int* in_sizes, int n_in,
                              void* d_out, int out_size){
    const float* reg_x   = (const float*)d_in[0];
    const int*   tok     = (const int*)d_in[1];
    const int*   rel_idx = (const int*)d_in[2];
    const float* emb_sum  = (const float*)d_in[5];
    const float* rel_emb0 = (const float*)d_in[6];
    const float* Wq  = (const float*)d_in[7];  const float* bq  = (const float*)d_in[8];
    const float* Wk  = (const float*)d_in[9];  const float* bk  = (const float*)d_in[10];
    const float* Wv  = (const float*)d_in[11]; const float* bv  = (const float*)d_in[12];
    const float* Wr0 = (const float*)d_in[13]; const float* br0 = (const float*)d_in[14];
    const float* Wk2 = (const float*)d_in[15]; const float* bk2 = (const float*)d_in[16];
    const float* Wv2 = (const float*)d_in[17]; const float* bv2 = (const float*)d_in[18];
    const float* Wo  = (const float*)d_in[19]; const float* bo  = (const float*)d_in[20];
    const float* lnkg  = (const float*)d_in[21]; const float* lnkb  = (const float*)d_in[22];
    const float* lnvg  = (const float*)d_in[23]; const float* lnvb  = (const float*)d_in[24];
    const float* lnk2g = (const float*)d_in[25]; const float* lnk2b = (const float*)d_in[26];
    const float* lnv2g = (const float*)d_in[27]; const float* lnv2b = (const float*)d_in[28];
    float* out = (float*)d_out;

    cudaFuncSetAttribute(attn_sum_kernel,  cudaFuncAttributeMaxDynamicSharedMemorySize, SUM_SMEM_BYTES);
    cudaFuncSetAttribute(attn_main_kernel, cudaFuncAttributeMaxDynamicSharedMemorySize, MAIN_SMEM_BYTES);
    cudaFuncSetAttribute(gemm_fused, cudaFuncAttributeMaxDynamicSharedMemorySize, GEMM_SMEM_BYTES);

    __half *xp, *attnp, *wqp, *wkp, *wvp, *wop;
    cudaGetSymbolAddress((void**)&xp, g_xp);
    cudaGetSymbolAddress((void**)&attnp, g_attnp);
    cudaGetSymbolAddress((void**)&wqp, g_Wqp);
    cudaGetSymbolAddress((void**)&wkp, g_Wkp);
    cudaGetSymbolAddress((void**)&wvp, g_Wvp);
    cudaGetSymbolAddress((void**)&wop, g_Wop);

    dim3 wgrid(32,32,4);
    dim3 wblk(32,8);
    dim3 ggrid(E_/128, MROWS/128);   // (8, 32)

    cvtA_kernel<<<MROWS*E_/4/256, 256>>>(reg_x, xp);                    // 1
    cvtW_kernel<<<wgrid, wblk>>>(Wq, Wk, Wv, Wo);                       // 2
    gemm_fused<<<ggrid, 256, GEMM_SMEM_BYTES>>>(xp, wkp, bk, (float*)0, 1, lnkg, lnkb); // 3
    gemm_fused<<<ggrid, 256, GEMM_SMEM_BYTES>>>(xp, wvp, bv, (float*)0, 2, lnvg, lnvb); // 4 (profiled)
    gemm_fused<<<ggrid, 256, GEMM_SMEM_BYTES>>>(xp, wqp, bq, (float*)0, 0, (const float*)0, (const float*)0); // 5
    r0_kernel<<<Z_*H_, 64>>>(rel_emb0, Wr0, br0);                       // 6
    idx8_kernel<<<(B_*TOTLEN*R_/4 + 255)/256, 256>>>(rel_idx);          // 7

    attn_sum_kernel<<<dim3(B_*H_, SPLITS), 128, SUM_SMEM_BYTES>>>(tok, emb_sum);
    combine_k2v2_kernel<<<B_*H_*S_, 64>>>(Wk2, bk2, Wv2, bv2, lnk2g, lnk2b, lnv2g, lnv2b);

    attn_main_kernel<<<dim3(R_/128, H_, B_), 128, MAIN_SMEM_BYTES>>>();

    gemm_fused<<<ggrid, 256, GEMM_SMEM_BYTES>>>(attnp, wop, bo, out, 3, (const float*)0, (const float*)0);
}